// round 15
// baseline (speedup 1.0000x reference)
#include <cuda_runtime.h>
#include <cuda_bf16.h>
#include <math.h>
#include <stdint.h>

#define NHEADS 16
#define DHEAD  64
#define DMODEL 1024
#define BATCH  2
#define QSCALE 0.125f
#define MAXTOK 1024
#define NU1 2047
#define NU2 1023
#define NU3 511
#define NUP1 2048
#define LNEPS 1e-9f
#define SLACK 4096
#define QKVSTR ((long)BATCH*MAXTOK*DMODEL)

// per-layer REL strides (float buffer and split buffer)
#define F1 ((long)16*64*NU1)
#define F2 ((long)16*64*NU2)
#define F3 ((long)16*64*NU3)
#define S1 ((long)16*32*NUP1)
#define S2 ((long)16*32*1024)
#define S3 ((long)16*32*512)

// ---------------- float scratch ----------------
__device__ float g_qkv[3*BATCH*MAXTOK*DMODEL];
__device__ float g_tmp[BATCH*MAXTOK*DMODEL];
__device__ float g_hA [BATCH*MAXTOK*DMODEL];
__device__ float g_hB [BATCH*MAXTOK*DMODEL];
__device__ float g_up [BATCH*MAXTOK*DMODEL];
__device__ float g_S  [(size_t)BATCH*NHEADS*MAXTOK*MAXTOK];
__device__ float g_P  [(size_t)BATCH*NHEADS*MAXTOK*NU1];
__device__ float g_RELF[16240640 + SLACK];   // 5*F1 + 4*F2 + 3*F3
__device__ float g_tt0[BATCH*NHEADS*MAXTOK];
__device__ float g_dtt[BATCH*NHEADS*MAXTOK];

// ---------------- split scratch (u32 = packed bf16 pair along k) ----------------
#define WSPL (12*512*1024)
__device__ __align__(16) uint32_t g_Wch[3*WSPL+SLACK], g_Wcl[3*WSPL+SLACK];
__device__ __align__(16) uint32_t g_Wph[WSPL+SLACK], g_Wpl[WSPL+SLACK];
__device__ __align__(16) uint32_t g_R1h[512*NUP1+SLACK], g_R1l[512*NUP1+SLACK];
__device__ __align__(16) uint32_t g_R2h[512*1024+SLACK], g_R2l[512*1024+SLACK];
__device__ __align__(16) uint32_t g_R3h[512*512+SLACK],  g_R3l[512*512+SLACK];
__device__ __align__(16) uint32_t g_rkTh[12*1024*512+SLACK], g_rkTl[12*1024*512+SLACK];
__device__ __align__(16) uint32_t g_RELh[8126464+SLACK], g_RELl[8126464+SLACK]; // 5*S1+4*S2+3*S3
__device__ __align__(16) uint32_t g_ksh[2*512*1024+SLACK], g_ksl[2*512*1024+SLACK];
__device__ __align__(16) uint32_t g_vsh[2*512*1024+SLACK], g_vsl[2*512*1024+SLACK];
__device__ __align__(16) uint32_t g_qwh[BATCH*MAXTOK*512+SLACK], g_qwl[BATCH*MAXTOK*512+SLACK];
__device__ __align__(16) uint32_t g_qqh[BATCH*MAXTOK*512+SLACK], g_qql[BATCH*MAXTOK*512+SLACK];
__device__ __align__(16) uint32_t g_Ssh[(size_t)BATCH*NHEADS*MAXTOK*512+SLACK];
__device__ __align__(16) uint32_t g_Ssl[(size_t)BATCH*NHEADS*MAXTOK*512+SLACK];
__device__ __align__(16) uint32_t g_vch[BATCH*MAXTOK*512+SLACK], g_vcl[BATCH*MAXTOK*512+SLACK];
__device__ __align__(16) uint32_t g_hsh[BATCH*MAXTOK*512+SLACK], g_hsl[BATCH*MAXTOK*512+SLACK];
__device__ __align__(16) uint32_t g_ush[BATCH*MAXTOK*512+SLACK], g_usl[BATCH*MAXTOK*512+SLACK];

// ---------------- helpers ----------------
__device__ __forceinline__ uint32_t pack_hi(float x0, float x1, uint32_t& lo) {
    __nv_bfloat16 h0 = __float2bfloat16_rn(x0);
    __nv_bfloat16 h1 = __float2bfloat16_rn(x1);
    float r0 = x0 - __bfloat162float(h0);
    float r1 = x1 - __bfloat162float(h1);
    __nv_bfloat162 hp; hp.x = h0; hp.y = h1;
    __nv_bfloat162 lp = __floats2bfloat162_rn(r0, r1);
    lo = *reinterpret_cast<uint32_t*>(&lp);
    return *reinterpret_cast<uint32_t*>(&hp);
}

__device__ __forceinline__ void mma16(float c[4], const uint32_t a[4], const uint32_t b[2]) {
    asm volatile(
        "mma.sync.aligned.m16n8k16.row.col.f32.bf16.bf16.f32 "
        "{%0,%1,%2,%3}, {%4,%5,%6,%7}, {%8,%9}, {%0,%1,%2,%3};"
        : "+f"(c[0]), "+f"(c[1]), "+f"(c[2]), "+f"(c[3])
        : "r"(a[0]), "r"(a[1]), "r"(a[2]), "r"(a[3]), "r"(b[0]), "r"(b[1]));
}

__device__ __forceinline__ float blockReduceSum(float v, float* red) {
    __syncthreads();
    #pragma unroll
    for (int o = 16; o > 0; o >>= 1) v += __shfl_down_sync(0xffffffffu, v, o);
    int lane = threadIdx.x & 31, w = threadIdx.x >> 5;
    if (lane == 0) red[w] = v;
    __syncthreads();
    int nw = (blockDim.x + 31) >> 5;
    if (w == 0) {
        v = (lane < nw) ? red[lane] : 0.f;
        #pragma unroll
        for (int o = 16; o > 0; o >>= 1) v += __shfl_down_sync(0xffffffffu, v, o);
        if (lane == 0) red[0] = v;
    }
    __syncthreads();
    return red[0];
}
__device__ __forceinline__ float blockReduceMax(float v, float* red) {
    __syncthreads();
    #pragma unroll
    for (int o = 16; o > 0; o >>= 1) v = fmaxf(v, __shfl_down_sync(0xffffffffu, v, o));
    int lane = threadIdx.x & 31, w = threadIdx.x >> 5;
    if (lane == 0) red[w] = v;
    __syncthreads();
    int nw = (blockDim.x + 31) >> 5;
    if (w == 0) {
        v = (lane < nw) ? red[lane] : -1e30f;
        #pragma unroll
        for (int o = 16; o > 0; o >>= 1) v = fmaxf(v, __shfl_down_sync(0xffffffffu, v, o));
        if (lane == 0) red[0] = v;
    }
    __syncthreads();
    return red[0];
}

// ---------------- unified split-input tensor-core GEMM (3xBF16) ----------------
#define ASTR 12
#define TSTR 136

__global__ __launch_bounds__(256, 2)
void gemm_tcs(const uint32_t* __restrict__ Ah_, const uint32_t* __restrict__ Al_,
              const uint32_t* __restrict__ Bh_, const uint32_t* __restrict__ Bl_,
              const float* __restrict__ bias, float* __restrict__ C,
              uint32_t* __restrict__ Ch, uint32_t* __restrict__ Cl,
              int M, int N, int Kp, int ldau, int ldbu, int ldc, int ldcs,
              long aO, long aI, long bO, long bI, long cO, long cI,
              int innerCount, float alpha, float biasAlpha,
              int posWin, int pcq, int pck, int pu0, int pLk)
{
    int rowBase = blockIdx.y * 128;
    int colBase = blockIdx.x * 128;
    if (posWin) {
        int r0 = rowBase, r1 = min(rowBase + 127, M - 1);
        int t1 = pcq * r0, t2 = pcq * r1;
        int umin = pu0 + min(t1, t2) + min(0, pck * (pLk - 1));
        int umax = pu0 + max(t1, t2) + max(0, pck * (pLk - 1));
        if (colBase > umax || colBase + 127 < umin) return;
    }
    int bz = blockIdx.z;
    int bo = bz / innerCount, bi = bz % innerCount;
    const uint32_t* Ahp = Ah_ + bo * aO + bi * aI;
    const uint32_t* Alp = Al_ + bo * aO + bi * aI;
    const uint32_t* Bhp = Bh_ + bo * bO + bi * bI;
    const uint32_t* Blp = Bl_ + bo * bO + bi * bI;

    __shared__ uint32_t Ash[128][ASTR], Asl[128][ASTR];
    __shared__ uint32_t Bsh[8][TSTR],  Bsl[8][TSTR];

    int tid = threadIdx.x, lane = tid & 31, warp = tid >> 5;
    int wm = warp & 1, wn = warp >> 1;
    int gid = lane >> 2, tig = lane & 3;

    int rowA = tid >> 1, halfA = (tid & 1) * 4;
    int kpB  = tid >> 5, nB = (tid & 31) * 4;
    bool aOk = (rowBase + rowA) < M;
    long aBase = (long)(rowBase + rowA) * ldau + halfA;
    long bBase = (long)kpB * ldbu + colBase + nB;

    // ldmatrix addresses for A fragments (loop-invariant)
    int arow = (lane < 16) ? lane : (lane - 16);
    int acol = (lane < 16) ? 0 : 4;
    uint32_t aAddrH[4], aAddrL[4];
    #pragma unroll
    for (int mi = 0; mi < 4; mi++) {
        int rm = wm * 64 + mi * 16;
        aAddrH[mi] = (uint32_t)__cvta_generic_to_shared(&Ash[rm + arow][acol]);
        aAddrL[mi] = (uint32_t)__cvta_generic_to_shared(&Asl[rm + arow][acol]);
    }

    float acc[4][4][4];
    #pragma unroll
    for (int a = 0; a < 4; a++)
        #pragma unroll
        for (int b = 0; b < 4; b++)
            #pragma unroll
            for (int c = 0; c < 4; c++) acc[a][b][c] = 0.f;

    uint4 zz = make_uint4(0, 0, 0, 0);
    uint4 ra_h = aOk ? *(const uint4*)(Ahp + aBase) : zz;
    uint4 ra_l = aOk ? *(const uint4*)(Alp + aBase) : zz;
    uint4 rb_h = *(const uint4*)(Bhp + bBase);
    uint4 rb_l = *(const uint4*)(Blp + bBase);

    for (int kp0 = 0; kp0 < Kp; kp0 += 8) {
        __syncthreads();
        *(uint4*)&Ash[rowA][halfA] = ra_h;
        *(uint4*)&Asl[rowA][halfA] = ra_l;
        *(uint4*)&Bsh[kpB][nB]     = rb_h;
        *(uint4*)&Bsl[kpB][nB]     = rb_l;
        __syncthreads();

        int kn = kp0 + 8;
        if (kn < Kp) {
            ra_h = aOk ? *(const uint4*)(Ahp + aBase + kn) : zz;
            ra_l = aOk ? *(const uint4*)(Alp + aBase + kn) : zz;
            rb_h = *(const uint4*)(Bhp + bBase + (long)kn * ldbu);
            rb_l = *(const uint4*)(Blp + bBase + (long)kn * ldbu);
        }

        uint32_t afh[4][4], afl[4][4];
        #pragma unroll
        for (int mi = 0; mi < 4; mi++) {
            asm volatile(
                "ldmatrix.sync.aligned.m8n8.x4.shared.b16 {%0,%1,%2,%3}, [%4];"
                : "=r"(afh[mi][0]), "=r"(afh[mi][1]), "=r"(afh[mi][2]), "=r"(afh[mi][3])
                : "r"(aAddrH[mi]));
            asm volatile(
                "ldmatrix.sync.aligned.m8n8.x4.shared.b16 {%0,%1,%2,%3}, [%4];"
                : "=r"(afl[mi][0]), "=r"(afl[mi][1]), "=r"(afl[mi][2]), "=r"(afl[mi][3])
                : "r"(aAddrL[mi]));
        }
        uint32_t bfh[4][2], bfl[4][2];
        #pragma unroll
        for (int ni = 0; ni < 4; ni++) {
            int cn = wn * 32 + ni * 8;
            bfh[ni][0] = Bsh[tig    ][cn + gid];
            bfh[ni][1] = Bsh[tig + 4][cn + gid];
            bfl[ni][0] = Bsl[tig    ][cn + gid];
            bfl[ni][1] = Bsl[tig + 4][cn + gid];
        }
        #pragma unroll
        for (int mi = 0; mi < 4; mi++)
            #pragma unroll
            for (int ni = 0; ni < 4; ni++) {
                mma16(acc[mi][ni], afh[mi], bfh[ni]);
                mma16(acc[mi][ni], afh[mi], bfl[ni]);
                mma16(acc[mi][ni], afl[mi], bfh[ni]);
            }
    }

    float*    Cp  = C  ? C  + bo * cO + bi * cI : (float*)0;
    uint32_t* Chp = Ch ? Ch + bo * cO + bi * cI : (uint32_t*)0;
    uint32_t* Clp = Cl ? Cl + bo * cO + bi * cI : (uint32_t*)0;

    #pragma unroll
    for (int mi = 0; mi < 4; mi++) {
        int r0 = rowBase + wm * 64 + mi * 16 + gid;
        int r1 = r0 + 8;
        #pragma unroll
        for (int ni = 0; ni < 4; ni++) {
            int c0 = colBase + wn * 32 + ni * 8 + tig * 2;
            int c1 = c0 + 1;
            float b0 = bias ? biasAlpha * bias[(c0 < N) ? c0 : 0] : 0.f;
            float b1 = bias ? biasAlpha * bias[(c1 < N) ? c1 : 0] : 0.f;
            if (Cp) {
                if (r0 < M && c0 < N) Cp[(long)r0 * ldc + c0] = alpha * acc[mi][ni][0] + b0;
                if (r0 < M && c1 < N) Cp[(long)r0 * ldc + c1] = alpha * acc[mi][ni][1] + b1;
                if (r1 < M && c0 < N) Cp[(long)r1 * ldc + c0] = alpha * acc[mi][ni][2] + b0;
                if (r1 < M && c1 < N) Cp[(long)r1 * ldc + c1] = alpha * acc[mi][ni][3] + b1;
            }
            if (Chp && c0 < N) {
                if (r0 < M) {
                    uint32_t lo, hi = pack_hi(alpha * acc[mi][ni][0] + b0,
                                              alpha * acc[mi][ni][1] + b1, lo);
                    Chp[(long)r0 * ldcs + (c0 >> 1)] = hi;
                    Clp[(long)r0 * ldcs + (c0 >> 1)] = lo;
                }
                if (r1 < M) {
                    uint32_t lo, hi = pack_hi(alpha * acc[mi][ni][2] + b0,
                                              alpha * acc[mi][ni][3] + b1, lo);
                    Chp[(long)r1 * ldcs + (c0 >> 1)] = hi;
                    Clp[(long)r1 * ldcs + (c0 >> 1)] = lo;
                }
            }
        }
    }
}

// ---------------- split kernels ----------------
__global__ void splitB_k(const float* __restrict__ src, uint32_t* __restrict__ dh,
                         uint32_t* __restrict__ dl, int Kp, int N, int dstLd,
                         long kStr, long nStr, long srcBOff, long dstBOff, int nBatch)
{
    long idx = (long)blockIdx.x * blockDim.x + threadIdx.x;
    long per = (long)Kp * dstLd;
    if (idx >= per * nBatch) return;
    int b = (int)(idx / per);
    long r = idx % per;
    int kp = (int)(r / dstLd), n = (int)(r % dstLd);
    float v0 = 0.f, v1 = 0.f;
    if (n < N) {
        const float* s = src + (long)b * srcBOff;
        v0 = s[(long)(2 * kp) * kStr + (long)n * nStr];
        v1 = s[(long)(2 * kp + 1) * kStr + (long)n * nStr];
    }
    uint32_t lo, hi = pack_hi(v0, v1, lo);
    dh[(long)b * dstBOff + r] = hi;
    dl[(long)b * dstBOff + r] = lo;
}

// A-format split (k contiguous): dst[m][kp]
__global__ void splitA_k(const float* __restrict__ src, uint32_t* __restrict__ dh,
                         uint32_t* __restrict__ dl, int M, int Kp, int lda)
{
    long idx = (long)blockIdx.x * blockDim.x + threadIdx.x;
    if (idx >= (long)M * Kp) return;
    int m = (int)(idx / Kp), kp = (int)(idx % Kp);
    float v0 = src[(long)m * lda + 2 * kp];
    float v1 = src[(long)m * lda + 2 * kp + 1];
    uint32_t lo, hi = pack_hi(v0, v1, lo);
    dh[idx] = hi; dl[idx] = lo;
}

// rkT split, tiled transpose, batched over layers via blockIdx.z
__global__ void rkTsplit_k(const float* __restrict__ rk, uint32_t* __restrict__ dh,
                           uint32_t* __restrict__ dl)
{
    int l = blockIdx.z;
    rk += (long)l * 1024 * 1024;
    dh += (long)l * 1024 * 512;
    dl += (long)l * 1024 * 512;
    __shared__ float ts[64][33];
    int nhBase = blockIdx.x * 32;
    int dBase  = blockIdx.y * 64;
    int tx = threadIdx.x, ty = threadIdx.y;   // 32 x 8
    #pragma unroll
    for (int dl_ = ty; dl_ < 64; dl_ += 8)
        ts[dl_][tx] = rk[(long)(dBase + dl_) * 1024 + nhBase + tx];
    __syncthreads();
    #pragma unroll
    for (int nl = ty; nl < 32; nl += 8) {
        uint32_t lo, hi = pack_hi(ts[2 * tx][nl], ts[2 * tx + 1][nl], lo);
        long o = (long)(nhBase + nl) * 512 + (dBase >> 1) + tx;
        dh[o] = hi; dl[o] = lo;
    }
}

// ---------------- fused per-layer prep: ksplit + vsplit + addbias2s + ttb ------
// One launch; block ranges select the sub-task. All sub-grids exact multiples.
__global__ void prep_k(const float* __restrict__ k, const float* __restrict__ v,
                       const float* __restrict__ q,
                       const float* __restrict__ bk, const float* __restrict__ bv,
                       const float* __restrict__ bq,
                       const float* __restrict__ rw, const float* __restrict__ rr,
                       const float* __restrict__ rs, const float* __restrict__ seg,
                       uint32_t* __restrict__ ksh, uint32_t* __restrict__ ksl,
                       uint32_t* __restrict__ vsh, uint32_t* __restrict__ vsl,
                       uint32_t* __restrict__ qwh, uint32_t* __restrict__ qwl,
                       uint32_t* __restrict__ qqh, uint32_t* __restrict__ qql,
                       float* __restrict__ tt0, float* __restrict__ dtt,
                       int Lk, int Lq, int nK, int nKV, int nKVA)
{
    int bid = blockIdx.x;
    int tx = threadIdx.x, ty = threadIdx.y;   // block (32, 8)
    int tid = ty * 32 + tx;

    if (bid < nK) {
        // ---- ksplit: tiled transpose, dst[b][dp][j] ----
        __shared__ float ts[32][65];
        int gx = Lk / 32;
        int b = bid / (gx * 16);
        int rem = bid % (gx * 16);
        int dTile = rem / gx;
        int jTile = rem % gx;
        int jBase = jTile * 32, dBase = dTile * 64;
        long per = (long)512 * Lk;
        const float* kb = k + (long)b * Lk * DMODEL;
        #pragma unroll
        for (int jl = ty; jl < 32; jl += 8) {
            ts[jl][tx]      = kb[(long)(jBase + jl) * DMODEL + dBase + tx];
            ts[jl][tx + 32] = kb[(long)(jBase + jl) * DMODEL + dBase + tx + 32];
        }
        __syncthreads();
        #pragma unroll
        for (int dpl = ty; dpl < 32; dpl += 8) {
            float b0 = bk[dBase + 2 * dpl], b1 = bk[dBase + 2 * dpl + 1];
            uint32_t lo, hi = pack_hi(ts[tx][2 * dpl] + b0, ts[tx][2 * dpl + 1] + b1, lo);
            long o = (long)b * per + (long)((dBase >> 1) + dpl) * Lk + jBase + tx;
            ksh[o] = hi; ksl[o] = lo;
        }
    } else if (bid < nKV) {
        // ---- vsplit: dst[b][jp][d] ----
        long idx = (long)(bid - nK) * 256 + tid;
        long per = (long)(Lk / 2) * DMODEL;
        if (idx < 2 * per) {
            int b = (int)(idx / per);
            long r = idx % per;
            int jp = (int)(r / DMODEL), d = (int)(r % DMODEL);
            float bb = bv[d];
            float v0 = v[((long)b * Lk + 2 * jp) * DMODEL + d] + bb;
            float v1 = v[((long)b * Lk + 2 * jp + 1) * DMODEL + d] + bb;
            uint32_t lo, hi = pack_hi(v0, v1, lo);
            vsh[(long)b * per + r] = hi;
            vsl[(long)b * per + r] = lo;
        }
    } else if (bid < nKVA) {
        // ---- addbias2s: qw/qq split ----
        long idx = (long)(bid - nKV) * 256 + tid;
        long total = (long)BATCH * Lq * 512;
        if (idx < total) {
            long row = idx / 512;
            int d2 = (int)(idx % 512);
            int d0 = 2 * d2, d1 = d0 + 1;
            float q0 = q[row * 1024 + d0] + bq[d0], q1 = q[row * 1024 + d1] + bq[d1];
            uint32_t lo, hi;
            hi = pack_hi(QSCALE * (q0 + rw[d0]), QSCALE * (q1 + rw[d1]), lo);
            qwh[idx] = hi; qwl[idx] = lo;
            hi = pack_hi(QSCALE * (q0 + rr[d0]), QSCALE * (q1 + rr[d1]), lo);
            qqh[idx] = hi; qql[idx] = lo;
        }
    } else {
        // ---- ttb: token-type biases ----
        int idx = (bid - nKVA) * 256 + tid;
        if (idx < BATCH * NHEADS * Lq) {
            int i = idx % Lq; int bn = idx / Lq; int n = bn % NHEADS; int b = bn / NHEADS;
            const float* qp  = q + ((long)(b * Lq + i)) * DMODEL + n * DHEAD;
            const float* bqp = bq + n * DHEAD;
            const float* rsp = rs + n * DHEAD;
            const float* s0  = seg + n * DHEAD;
            const float* s1  = seg + DMODEL + n * DHEAD;
            float t0 = 0.f, t1 = 0.f;
            #pragma unroll 8
            for (int h = 0; h < DHEAD; h++) {
                float vq = QSCALE * (qp[h] + bqp[h] + rsp[h]);
                t0 += vq * s0[h];
                t1 += vq * s1[h];
            }
            tt0[(long)bn * Lq + i] = t0;
            dtt[(long)bn * Lq + i] = t1 - t0;
        }
    }
}

// ---------------- relative-position basis, generated directly in split form ----
__global__ void relmat_split_k(uint32_t* __restrict__ dh, uint32_t* __restrict__ dl,
                               int nU, int nUp, int g, int d0)
{
    long idx = (long)blockIdx.x * blockDim.x + threadIdx.x;
    long tot = (long)512 * nUp;
    if (idx >= tot) return;
    int kp = (int)(idx / nUp), u = (int)(idx % nUp);
    float v0 = 0.f, v1 = 0.f;
    if (u < nU) {
        int da = 2 * kp, db_ = 2 * kp + 1;
        int fa = (da < 512) ? da : da - 512;
        int fb = (db_ < 512) ? db_ : db_ - 512;
        float invfa = expf(-(float)fa * (9.210340371976184f / 512.0f));
        float invfb = expf(-(float)fb * (9.210340371976184f / 512.0f));
        float base = (float)(g * u + d0);
        float aa = base * invfa, ab = base * invfb;
        v0 = (da < 512) ? sinf(aa) : cosf(aa);
        v1 = (db_ < 512) ? sinf(ab) : cosf(ab);
    }
    uint32_t lo, hi = pack_hi(v0, v1, lo);
    dh[idx] = hi; dl[idx] = lo;
}

// assemble scores (content + rel-pos gather + token-type) and softmax; split probs out
__global__ void softmax_k(const float* __restrict__ S, const float* __restrict__ P,
                          uint32_t* __restrict__ Sh, uint32_t* __restrict__ Sl,
                          const float* __restrict__ tt0, const float* __restrict__ dtt,
                          const int* __restrict__ ids,
                          int Lq, int Lk, int nU, int cq, int ck, int u0, int pq, int pk)
{
    int i = blockIdx.x, n = blockIdx.y, b = blockIdx.z;
    int bn = b * NHEADS + n;
    const float* Srow = S + ((long)bn * Lq + i) * Lk;
    const float* Prow = P + ((long)bn * Lq + i) * nU;
    float t0 = tt0[(long)bn * Lq + i], dt = dtt[(long)bn * Lq + i];
    const int* idk = ids + b * 1024;
    int idq = idk[pq * i];
    int ubase = cq * i + u0;

    __shared__ float sh[MAXTOK];
    __shared__ float red[32];
    int tid = threadIdx.x;

    float lmax = -1e30f;
    for (int j = tid; j < Lk; j += blockDim.x) {
        float tok = (idk[pk * j] == idq) ? (t0 + dt) : t0;
        float v = Srow[j] + Prow[ubase + ck * j] + tok;
        sh[j] = v;
        lmax = fmaxf(lmax, v);
    }
    float bmax = blockReduceMax(lmax, red);

    float lsum = 0.f;
    for (int j = tid; j < Lk; j += blockDim.x) {
        float e = expf(sh[j] - bmax);
        sh[j] = e;
        lsum += e;
    }
    float bsum = blockReduceSum(lsum, red);
    float inv = 1.0f / bsum;

    long srow = ((long)bn * Lq + i) * (Lk >> 1);
    for (int j2 = tid; j2 < (Lk >> 1); j2 += blockDim.x) {
        uint32_t lo, hi = pack_hi(sh[2 * j2] * inv, sh[2 * j2 + 1] * inv, lo);
        Sh[srow + j2] = hi;
        Sl[srow + j2] = lo;
    }
}

// residual + LayerNorm; writes float out + split out
__global__ void ln_k(const float* __restrict__ qin, const float* __restrict__ tmp,
                     const float* __restrict__ gvec, const float* __restrict__ bvec,
                     float* __restrict__ out, uint32_t* __restrict__ oh,
                     uint32_t* __restrict__ ol)
{
    int r = blockIdx.x, tid = threadIdx.x;
    const float* x1 = qin + (long)r * DMODEL;
    const float* x2 = tmp + (long)r * DMODEL;
    __shared__ float red[32];
    float s = 0.f;
    for (int d = tid; d < DMODEL; d += blockDim.x) s += x1[d] + x2[d];
    float mu = blockReduceSum(s, red) * (1.0f / DMODEL);
    float vs = 0.f;
    for (int d = tid; d < DMODEL; d += blockDim.x) {
        float z = x1[d] + x2[d] - mu;
        vs += z * z;
    }
    float var = blockReduceSum(vs, red) * (1.0f / DMODEL);
    float rstd = rsqrtf(var + LNEPS);
    for (int d2 = tid; d2 < 512; d2 += blockDim.x) {
        int d0 = 2 * d2, d1 = d0 + 1;
        float o0 = (x1[d0] + x2[d0] - mu) * rstd * gvec[d0] + bvec[d0];
        float o1 = (x1[d1] + x2[d1] - mu) * rstd * gvec[d1] + bvec[d1];
        out[(long)r * DMODEL + d0] = o0;
        out[(long)r * DMODEL + d1] = o1;
        uint32_t lo, hi = pack_hi(o0, o1, lo);
        oh[(long)r * 512 + d2] = hi;
        ol[(long)r * 512 + d2] = lo;
    }
}

// upsample; writes float out + split out
__global__ void upsample_k(const float* __restrict__ h, float* __restrict__ out,
                           uint32_t* __restrict__ oh, uint32_t* __restrict__ ol, int Lin)
{
    long idx = (long)blockIdx.x * blockDim.x + threadIdx.x;
    long total = (long)BATCH * Lin * 512;
    if (idx >= total) return;
    int d2 = (int)(idx % 512);
    long bt = idx / 512;
    int t = (int)(bt % Lin);
    int b = (int)(bt / Lin);
    int tp = (t == 0) ? Lin - 1 : t - 1;
    const float* cr = h + ((long)b * Lin + t) * DMODEL + 2 * d2;
    const float* pr = h + ((long)b * Lin + tp) * DMODEL + 2 * d2;
    float c0 = cr[0], c1 = cr[1];
    float i0 = 0.5f * (c0 + pr[0]), i1 = 0.5f * (c1 + pr[1]);
    long r = (long)b * (2 * Lin) + 2 * t;
    out[r * DMODEL + 2 * d2]     = c0;
    out[r * DMODEL + 2 * d2 + 1] = c1;
    out[(r + 1) * DMODEL + 2 * d2]     = i0;
    out[(r + 1) * DMODEL + 2 * d2 + 1] = i1;
    uint32_t lo, hi = pack_hi(c0, c1, lo);
    oh[r * 512 + d2] = hi; ol[r * 512 + d2] = lo;
    hi = pack_hi(i0, i1, lo);
    oh[(r + 1) * 512 + d2] = hi; ol[(r + 1) * 512 + d2] = lo;
}

// ---------------- host ----------------
static void gemmS(const uint32_t* Ah, const uint32_t* Al,
                  const uint32_t* Bh, const uint32_t* Bl,
                  const float* bias, float* C, uint32_t* Ch, uint32_t* Cl,
                  int M, int N, int Kp, int ldau, int ldbu, int ldc, int ldcs,
                  long aO, long aI, long bO, long bI, long cO, long cI,
                  int innerCount, int batches, float alpha, float biasAlpha,
                  int posWin = 0, int pcq = 0, int pck = 0, int pu0 = 0, int pLk = 0)
{
    dim3 grid((N + 127) / 128, (M + 127) / 128, batches);
    gemm_tcs<<<grid, 256>>>(Ah, Al, Bh, Bl, bias, C, Ch, Cl,
                            M, N, Kp, ldau, ldbu, ldc, ldcs,
                            aO, aI, bO, bI, cO, cI, innerCount, alpha, biasAlpha,
                            posWin, pcq, pck, pu0, pLk);
}

static long relSoff(int l) {
    if (l <= 4) return (long)l * S1;
    if (l <= 8) return 5 * S1 + (long)(l - 5) * S2;
    return 5 * S1 + 4 * S2 + (long)(l - 9) * S3;
}

#define GS(sym, var) cudaGetSymbolAddress((void**)&var, sym)

extern "C" void kernel_launch(void* const* d_in, const int* in_sizes, int n_in,
                              void* d_out, int out_size)
{
    const float* final_hidden = (const float*)d_in[0];
    const int*   tok_ids      = (const int*)d_in[5];
    const float* Wq = (const float*)d_in[6];
    const float* bq = (const float*)d_in[7];
    const float* Wk = (const float*)d_in[8];
    const float* bk = (const float*)d_in[9];
    const float* Wv = (const float*)d_in[10];
    const float* bv = (const float*)d_in[11];
    const float* rw = (const float*)d_in[12];
    const float* rr = (const float*)d_in[13];
    const float* rs = (const float*)d_in[14];
    const float* rk = (const float*)d_in[15];
    const float* sg = (const float*)d_in[16];
    const float* Wp = (const float*)d_in[17];
    const float* bp = (const float*)d_in[18];
    const float* lg = (const float*)d_in[19];
    const float* lb = (const float*)d_in[20];
    float* out = (float*)d_out;

    float *p_qkv,*p_tmp,*p_hA,*p_hB,*p_up,*p_S,*p_P,*p_RELF,*p_t0,*p_dt;
    GS(g_qkv,p_qkv); GS(g_tmp,p_tmp);
    GS(g_hA,p_hA); GS(g_hB,p_hB); GS(g_up,p_up);
    GS(g_S,p_S); GS(g_P,p_P); GS(g_RELF,p_RELF);
    GS(g_tt0,p_t0); GS(g_dtt,p_dt);

    uint32_t *wch,*wcl,*wph,*wpl;
    uint32_t *r1h,*r1l,*r2h,*r2l,*r3h,*r3l,*rkth,*rktl,*relh,*rell;
    uint32_t *ksh,*ksl,*vsh,*vsl,*qwh,*qwl,*qqh,*qql,*ssh,*ssl,*vch,*vcl,*hsh,*hsl,*ush,*usl;
    GS(g_Wch,wch); GS(g_Wcl,wcl); GS(g_Wph,wph); GS(g_Wpl,wpl);
    GS(g_R1h,r1h); GS(g_R1l,r1l); GS(g_R2h,r2h); GS(g_R2l,r2l); GS(g_R3h,r3h); GS(g_R3l,r3l);
    GS(g_rkTh,rkth); GS(g_rkTl,rktl); GS(g_RELh,relh); GS(g_RELl,rell);
    GS(g_ksh,ksh); GS(g_ksl,ksl); GS(g_vsh,vsh); GS(g_vsl,vsl);
    GS(g_qwh,qwh); GS(g_qwl,qwl); GS(g_qqh,qqh); GS(g_qql,qql);
    GS(g_Ssh,ssh); GS(g_Ssl,ssl); GS(g_vch,vch); GS(g_vcl,vcl);
    GS(g_hsh,hsh); GS(g_hsl,hsl); GS(g_ush,ush); GS(g_usl,usl);

    // ---- setup: rel-pos bases + weight splits ----
    relmat_split_k<<<(512*NUP1 + 255)/256, 256>>>(r1h, r1l, NU1, NUP1, 1, -1023);
    relmat_split_k<<<(512*1024 + 255)/256, 256>>>(r2h, r2l, NU2, 1024, 2, -1022);
    relmat_split_k<<<(512*512  + 255)/256, 256>>>(r3h, r3l, NU3, 512,  4, -1020);
    {
        long t = (long)6144*1024;
        splitB_k<<<(unsigned)((t+255)/256),256>>>(Wq, wch,          wcl,          6144, 1024, 1024, 1024, 1, 0, 0, 1);
        splitB_k<<<(unsigned)((t+255)/256),256>>>(Wk, wch + WSPL,   wcl + WSPL,   6144, 1024, 1024, 1024, 1, 0, 0, 1);
        splitB_k<<<(unsigned)((t+255)/256),256>>>(Wv, wch + 2*WSPL, wcl + 2*WSPL, 6144, 1024, 1024, 1024, 1, 0, 0, 1);
        splitB_k<<<(unsigned)((t+255)/256),256>>>(Wp, wph, wpl, 6144, 1024, 1024, 1024, 1, 0, 0, 1);
        t = (long)512*512;  splitA_k<<<(unsigned)((t+255)/256),256>>>(final_hidden, hsh, hsl, 512, 512, 1024);
    }

    // ---- hoisted REL pipeline: all 12 layers, batched by R-group ----
    {
        dim3 tb(32, 8), tg(32, 16, 12);
        rkTsplit_k<<<tg, tb>>>(rk, rkth, rktl);
    }
    gemmS(rkth, rktl, r1h, r1l, nullptr, p_RELF, nullptr, nullptr,
          1024, NU1, 512, 512, NUP1, NU1, 0,
          0, (long)1024*512, 0, 0, 0, F1,
          5, 5, 1.f, 0.f);
    gemmS(rkth + (long)5*1024*512, rktl + (long)5*1024*512, r2h, r2l, nullptr,
          p_RELF + 5*F1, nullptr, nullptr,
          1024, NU2, 512, 512, 1024, NU2, 0,
          0, (long)1024*512, 0, 0, 0, F2,
          4, 4, 1.f, 0.f);
    gemmS(rkth + (long)9*1024*512, rktl + (long)9*1024*512, r3h, r3l, nullptr,
          p_RELF + 5*F1 + 4*F2, nullptr, nullptr,
          1024, NU3, 512, 512, 512, NU3, 0,
          0, (long)1024*512, 0, 0, 0, F3,
          3, 3, 1.f, 0.f);
    {
        long t;
        t = (long)80*32*NUP1;
        splitB_k<<<(unsigned)((t+255)/256),256>>>(p_RELF, relh, rell, 32, NU1, NUP1,
                                                  NU1, 1, (long)64*NU1, (long)32*NUP1, 80);
        t = (long)64*32*1024;
        splitB_k<<<(unsigned)((t+255)/256),256>>>(p_RELF + 5*F1, relh + 5*S1, rell + 5*S1,
                                                  32, NU2, 1024, NU2, 1, (long)64*NU2, (long)32*1024, 64);
        t = (long)48*32*512;
        splitB_k<<<(unsigned)((t+255)/256),256>>>(p_RELF + 5*F1 + 4*F2, relh + 5*S1 + 4*S2,
                                                  rell + 5*S1 + 4*S2,
                                                  32, NU3, 512, NU3, 1, (long)64*NU3, (long)32*512, 48);
    }

    const float* hidden = final_hidden;
    float* bufs[2] = {p_hA, p_hB};
    int pb = 0;

    for (int l = 11; l >= 0; --l) {
        int Lq, Lk, do_up, nU, nUp, cq, ck, u0, pq, pk;
        if (l <= 3)      { Lq=1024; Lk=1024; do_up=0; nU=NU1; nUp=NUP1; cq= 1; ck=-1; u0=1023; pq=1; pk=1; }
        else if (l == 4) { Lq=1024; Lk=512;  do_up=1; nU=NU1; nUp=NUP1; cq=-1; ck= 2; u0=1023; pq=1; pk=2; }
        else if (l <= 7) { Lq=512;  Lk=512;  do_up=0; nU=NU2; nUp=1024; cq= 1; ck=-1; u0=511;  pq=2; pk=2; }
        else if (l == 8) { Lq=512;  Lk=256;  do_up=1; nU=NU2; nUp=1024; cq=-1; ck= 2; u0=511;  pq=2; pk=4; }
        else             { Lq=256;  Lk=256;  do_up=0; nU=NU3; nUp=512;  cq= 1; ck=-1; u0=255;  pq=4; pk=4; }

        if (l == 11) { long t = (long)BATCH*256*512; upsample_k<<<(unsigned)((t+255)/256),256>>>(hidden, p_up, ush, usl, 256); }
        if (l == 7)  { long t = (long)BATCH*512*512; upsample_k<<<(unsigned)((t+255)/256),256>>>(hidden, p_up, ush, usl, 512); }

        const float* q_in_f = do_up ? p_up : hidden;
        uint32_t* qinh = do_up ? ush : hsh;
        uint32_t* qinl = do_up ? usl : hsl;
        uint32_t* relh_l = relh + relSoff(l);
        uint32_t* rell_l = rell + relSoff(l);

        float* p_q = p_qkv;
        float* p_k = p_qkv + QKVSTR;
        float* p_v = p_qkv + 2 * QKVSTR;

        // merged QKV projections (no bias; folded downstream)
        long WO = (long)WSPL;
        if (do_up) {
            gemmS(qinh, qinl, wch + (long)l*512*1024, wcl + (long)l*512*1024, nullptr,
                  p_q, nullptr, nullptr,
                  BATCH*Lq, DMODEL, 512, 512, 1024, DMODEL, 0,
                  0,0,0,0,0,0, 1, 1, 1.f, 0.f);
            gemmS(hsh, hsl, wch + WO + (long)l*512*1024, wcl + WO + (long)l*512*1024, nullptr,
                  p_k, nullptr, nullptr,
                  BATCH*Lk, DMODEL, 512, 512, 1024, DMODEL, 0,
                  0, 0, WO, 0, QKVSTR, 0,
                  1, 2, 1.f, 0.f);
        } else {
            gemmS(hsh, hsl, wch + (long)l*512*1024, wcl + (long)l*512*1024, nullptr,
                  p_q, nullptr, nullptr,
                  BATCH*Lq, DMODEL, 512, 512, 1024, DMODEL, 0,
                  0, 0, WO, 0, QKVSTR, 0,
                  1, 3, 1.f, 0.f);
        }

        // fused prep: ksplit + vsplit + addbias2s + ttb in ONE launch
        {
            int nK   = (Lk / 32) * 16 * 2;
            int nKV  = nK + 4 * Lk;
            int nKVA = nKV + 4 * Lq;
            int tot  = nKVA + Lq / 8;
            dim3 tb(32, 8);
            prep_k<<<tot, tb>>>(p_k, p_v, p_q,
                                bk + l*DMODEL, bv + l*DMODEL, bq + l*DMODEL,
                                rw + l*DMODEL, rr + l*DMODEL, rs + l*DMODEL,
                                sg + (long)l*2*DMODEL,
                                ksh, ksl, vsh, vsl, qwh, qwl, qqh, qql,
                                p_t0, p_dt, Lk, Lq, nK, nKV, nKVA);
        }

        // content scores -> S
        gemmS(qwh, qwl, ksh, ksl, nullptr, p_S, nullptr, nullptr,
              Lq, Lk, 32, 512, Lk, Lk, 0,
              (long)Lq*512, 32, (long)512*Lk, (long)32*Lk,
              (long)NHEADS*Lq*Lk, (long)Lq*Lk,
              NHEADS, BATCH*NHEADS, 1.f, 0.f);

        // P (rel-pos projections), window-culled
        gemmS(qqh, qql, relh_l, rell_l, nullptr, p_P, nullptr, nullptr,
              Lq, nU, 32, 512, nUp, nU, 0,
              (long)Lq*512, 32, 0, (long)32*nUp,
              (long)NHEADS*Lq*nU, (long)Lq*nU,
              NHEADS, BATCH*NHEADS, 1.f, 0.f,
              1, cq, ck, u0, Lk);

        // softmax (gathers P band, writes split probs)
        {
            dim3 grid(Lq, NHEADS, BATCH);
            softmax_k<<<grid, 256>>>(p_S, p_P, ssh, ssl, p_t0, p_dt, tok_ids,
                                     Lq, Lk, nU, cq, ck, u0, pq, pk);
        }

        // vec = prob @ v (split output)
        gemmS(ssh, ssl, vsh, vsl, nullptr, nullptr, vch, vcl,
              Lq, DHEAD, Lk/2, Lk/2, DMODEL, 0, 512,
              (long)NHEADS*Lq*(Lk/2), (long)Lq*(Lk/2),
              (long)(Lk/2)*DMODEL, 64,
              (long)Lq*512, 32,
              NHEADS, BATCH*NHEADS, 1.f, 0.f);

        // post projection
        gemmS(vch, vcl, wph + (long)l*512*1024, wpl + (long)l*512*1024, bp + l*DMODEL,
              p_tmp, nullptr, nullptr,
              BATCH*Lq, DMODEL, 512, 512, 1024, DMODEL, 0,
              0,0,0,0,0,0, 1, 1, 1.f, 1.f);

        // residual + LayerNorm (writes float hidden + split hidden)
        float* dst = (l == 0) ? out : bufs[pb];
        ln_k<<<BATCH*Lq, 256>>>(q_in_f, p_tmp, lg + l*DMODEL, lb + l*DMODEL, dst, hsh, hsl);

        hidden = dst;
        pb ^= 1;
    }
}

// round 16
// speedup vs baseline: 1.0090x; 1.0090x over previous
#include <cuda_runtime.h>
#include <cuda_bf16.h>
#include <math.h>
#include <stdint.h>

#define NHEADS 16
#define DHEAD  64
#define DMODEL 1024
#define BATCH  2
#define QSCALE 0.125f
#define MAXTOK 1024
#define NU1 2047
#define NU2 1023
#define NU3 511
#define NUP1 2048
#define LNEPS 1e-9f
#define SLACK 4096
#define QKVSTR ((long)BATCH*MAXTOK*DMODEL)

// per-layer REL strides (float buffer and split buffer)
#define F1 ((long)16*64*NU1)
#define F2 ((long)16*64*NU2)
#define F3 ((long)16*64*NU3)
#define S1 ((long)16*32*NUP1)
#define S2 ((long)16*32*1024)
#define S3 ((long)16*32*512)

// ---------------- float scratch ----------------
__device__ float g_qkv[3*BATCH*MAXTOK*DMODEL];
__device__ float g_tmp[BATCH*MAXTOK*DMODEL];
__device__ float g_hA [BATCH*MAXTOK*DMODEL];
__device__ float g_hB [BATCH*MAXTOK*DMODEL];
__device__ float g_up [BATCH*MAXTOK*DMODEL];
__device__ float g_S  [(size_t)BATCH*NHEADS*MAXTOK*MAXTOK];
__device__ float g_P  [(size_t)BATCH*NHEADS*MAXTOK*NU1];
__device__ float g_RELF[16240640 + SLACK];   // 5*F1 + 4*F2 + 3*F3
__device__ float g_tt0[BATCH*NHEADS*MAXTOK];
__device__ float g_dtt[BATCH*NHEADS*MAXTOK];

// ---------------- split scratch (u32 = packed bf16 pair along k) ----------------
#define WSPL (12*512*1024)
__device__ __align__(16) uint32_t g_Wch[3*WSPL+SLACK], g_Wcl[3*WSPL+SLACK];
__device__ __align__(16) uint32_t g_Wph[WSPL+SLACK], g_Wpl[WSPL+SLACK];
__device__ __align__(16) uint32_t g_R1h[512*NUP1+SLACK], g_R1l[512*NUP1+SLACK];
__device__ __align__(16) uint32_t g_R2h[512*1024+SLACK], g_R2l[512*1024+SLACK];
__device__ __align__(16) uint32_t g_R3h[512*512+SLACK],  g_R3l[512*512+SLACK];
__device__ __align__(16) uint32_t g_rkTh[12*1024*512+SLACK], g_rkTl[12*1024*512+SLACK];
__device__ __align__(16) uint32_t g_RELh[8126464+SLACK], g_RELl[8126464+SLACK]; // 5*S1+4*S2+3*S3
__device__ __align__(16) uint32_t g_ksh[2*512*1024+SLACK], g_ksl[2*512*1024+SLACK];
__device__ __align__(16) uint32_t g_vsh[2*512*1024+SLACK], g_vsl[2*512*1024+SLACK];
__device__ __align__(16) uint32_t g_qwh[BATCH*MAXTOK*512+SLACK], g_qwl[BATCH*MAXTOK*512+SLACK];
__device__ __align__(16) uint32_t g_qqh[BATCH*MAXTOK*512+SLACK], g_qql[BATCH*MAXTOK*512+SLACK];
__device__ __align__(16) uint32_t g_Ssh[(size_t)BATCH*NHEADS*MAXTOK*512+SLACK];
__device__ __align__(16) uint32_t g_Ssl[(size_t)BATCH*NHEADS*MAXTOK*512+SLACK];
__device__ __align__(16) uint32_t g_vch[BATCH*MAXTOK*512+SLACK], g_vcl[BATCH*MAXTOK*512+SLACK];
__device__ __align__(16) uint32_t g_hsh[BATCH*MAXTOK*512+SLACK], g_hsl[BATCH*MAXTOK*512+SLACK];
__device__ __align__(16) uint32_t g_ush[BATCH*MAXTOK*512+SLACK], g_usl[BATCH*MAXTOK*512+SLACK];

// ---------------- helpers ----------------
__device__ __forceinline__ uint32_t pack_hi(float x0, float x1, uint32_t& lo) {
    __nv_bfloat16 h0 = __float2bfloat16_rn(x0);
    __nv_bfloat16 h1 = __float2bfloat16_rn(x1);
    float r0 = x0 - __bfloat162float(h0);
    float r1 = x1 - __bfloat162float(h1);
    __nv_bfloat162 hp; hp.x = h0; hp.y = h1;
    __nv_bfloat162 lp = __floats2bfloat162_rn(r0, r1);
    lo = *reinterpret_cast<uint32_t*>(&lp);
    return *reinterpret_cast<uint32_t*>(&hp);
}

__device__ __forceinline__ void mma16(float c[4], const uint32_t a[4], const uint32_t b[2]) {
    asm volatile(
        "mma.sync.aligned.m16n8k16.row.col.f32.bf16.bf16.f32 "
        "{%0,%1,%2,%3}, {%4,%5,%6,%7}, {%8,%9}, {%0,%1,%2,%3};"
        : "+f"(c[0]), "+f"(c[1]), "+f"(c[2]), "+f"(c[3])
        : "r"(a[0]), "r"(a[1]), "r"(a[2]), "r"(a[3]), "r"(b[0]), "r"(b[1]));
}

__device__ __forceinline__ float blockReduceSum(float v, float* red) {
    __syncthreads();
    #pragma unroll
    for (int o = 16; o > 0; o >>= 1) v += __shfl_down_sync(0xffffffffu, v, o);
    int lane = threadIdx.x & 31, w = threadIdx.x >> 5;
    if (lane == 0) red[w] = v;
    __syncthreads();
    int nw = (blockDim.x + 31) >> 5;
    if (w == 0) {
        v = (lane < nw) ? red[lane] : 0.f;
        #pragma unroll
        for (int o = 16; o > 0; o >>= 1) v += __shfl_down_sync(0xffffffffu, v, o);
        if (lane == 0) red[0] = v;
    }
    __syncthreads();
    return red[0];
}
__device__ __forceinline__ float blockReduceMax(float v, float* red) {
    __syncthreads();
    #pragma unroll
    for (int o = 16; o > 0; o >>= 1) v = fmaxf(v, __shfl_down_sync(0xffffffffu, v, o));
    int lane = threadIdx.x & 31, w = threadIdx.x >> 5;
    if (lane == 0) red[w] = v;
    __syncthreads();
    int nw = (blockDim.x + 31) >> 5;
    if (w == 0) {
        v = (lane < nw) ? red[lane] : -1e30f;
        #pragma unroll
        for (int o = 16; o > 0; o >>= 1) v = fmaxf(v, __shfl_down_sync(0xffffffffu, v, o));
        if (lane == 0) red[0] = v;
    }
    __syncthreads();
    return red[0];
}

// ---------------- unified split-input tensor-core GEMM (3xBF16) ----------------
#define ASTR 12
#define TSTR 136

__global__ __launch_bounds__(256, 2)
void gemm_tcs(const uint32_t* __restrict__ Ah_, const uint32_t* __restrict__ Al_,
              const uint32_t* __restrict__ Bh_, const uint32_t* __restrict__ Bl_,
              const float* __restrict__ bias, float* __restrict__ C,
              uint32_t* __restrict__ Ch, uint32_t* __restrict__ Cl,
              int M, int N, int Kp, int ldau, int ldbu, int ldc, int ldcs,
              long aO, long aI, long bO, long bI, long cO, long cI,
              int innerCount, float alpha, float biasAlpha,
              int posWin, int pcq, int pck, int pu0, int pLk)
{
    int rowBase = blockIdx.y * 128;
    int colBase = blockIdx.x * 128;
    if (posWin) {
        int r0 = rowBase, r1 = min(rowBase + 127, M - 1);
        int t1 = pcq * r0, t2 = pcq * r1;
        int umin = pu0 + min(t1, t2) + min(0, pck * (pLk - 1));
        int umax = pu0 + max(t1, t2) + max(0, pck * (pLk - 1));
        if (colBase > umax || colBase + 127 < umin) return;
    }
    int bz = blockIdx.z;
    int bo = bz / innerCount, bi = bz % innerCount;
    const uint32_t* Ahp = Ah_ + bo * aO + bi * aI;
    const uint32_t* Alp = Al_ + bo * aO + bi * aI;
    const uint32_t* Bhp = Bh_ + bo * bO + bi * bI;
    const uint32_t* Blp = Bl_ + bo * bO + bi * bI;

    __shared__ uint32_t Ash[128][ASTR], Asl[128][ASTR];
    __shared__ uint32_t Bsh[8][TSTR],  Bsl[8][TSTR];

    int tid = threadIdx.x, lane = tid & 31, warp = tid >> 5;
    int wm = warp & 1, wn = warp >> 1;
    int gid = lane >> 2, tig = lane & 3;

    int rowA = tid >> 1, halfA = (tid & 1) * 4;
    int kpB  = tid >> 5, nB = (tid & 31) * 4;
    bool aOk = (rowBase + rowA) < M;
    long aBase = (long)(rowBase + rowA) * ldau + halfA;
    long bBase = (long)kpB * ldbu + colBase + nB;

    // ldmatrix addresses for A fragments (loop-invariant)
    int arow = (lane < 16) ? lane : (lane - 16);
    int acol = (lane < 16) ? 0 : 4;
    uint32_t aAddrH[4], aAddrL[4];
    #pragma unroll
    for (int mi = 0; mi < 4; mi++) {
        int rm = wm * 64 + mi * 16;
        aAddrH[mi] = (uint32_t)__cvta_generic_to_shared(&Ash[rm + arow][acol]);
        aAddrL[mi] = (uint32_t)__cvta_generic_to_shared(&Asl[rm + arow][acol]);
    }

    float acc[4][4][4];
    #pragma unroll
    for (int a = 0; a < 4; a++)
        #pragma unroll
        for (int b = 0; b < 4; b++)
            #pragma unroll
            for (int c = 0; c < 4; c++) acc[a][b][c] = 0.f;

    uint4 zz = make_uint4(0, 0, 0, 0);
    uint4 ra_h = aOk ? *(const uint4*)(Ahp + aBase) : zz;
    uint4 ra_l = aOk ? *(const uint4*)(Alp + aBase) : zz;
    uint4 rb_h = *(const uint4*)(Bhp + bBase);
    uint4 rb_l = *(const uint4*)(Blp + bBase);

    for (int kp0 = 0; kp0 < Kp; kp0 += 8) {
        __syncthreads();
        *(uint4*)&Ash[rowA][halfA] = ra_h;
        *(uint4*)&Asl[rowA][halfA] = ra_l;
        *(uint4*)&Bsh[kpB][nB]     = rb_h;
        *(uint4*)&Bsl[kpB][nB]     = rb_l;
        __syncthreads();

        int kn = kp0 + 8;
        if (kn < Kp) {
            ra_h = aOk ? *(const uint4*)(Ahp + aBase + kn) : zz;
            ra_l = aOk ? *(const uint4*)(Alp + aBase + kn) : zz;
            rb_h = *(const uint4*)(Bhp + bBase + (long)kn * ldbu);
            rb_l = *(const uint4*)(Blp + bBase + (long)kn * ldbu);
        }

        uint32_t afh[4][4], afl[4][4];
        #pragma unroll
        for (int mi = 0; mi < 4; mi++) {
            asm volatile(
                "ldmatrix.sync.aligned.m8n8.x4.shared.b16 {%0,%1,%2,%3}, [%4];"
                : "=r"(afh[mi][0]), "=r"(afh[mi][1]), "=r"(afh[mi][2]), "=r"(afh[mi][3])
                : "r"(aAddrH[mi]));
            asm volatile(
                "ldmatrix.sync.aligned.m8n8.x4.shared.b16 {%0,%1,%2,%3}, [%4];"
                : "=r"(afl[mi][0]), "=r"(afl[mi][1]), "=r"(afl[mi][2]), "=r"(afl[mi][3])
                : "r"(aAddrL[mi]));
        }
        uint32_t bfh[4][2], bfl[4][2];
        #pragma unroll
        for (int ni = 0; ni < 4; ni++) {
            int cn = wn * 32 + ni * 8;
            bfh[ni][0] = Bsh[tig    ][cn + gid];
            bfh[ni][1] = Bsh[tig + 4][cn + gid];
            bfl[ni][0] = Bsl[tig    ][cn + gid];
            bfl[ni][1] = Bsl[tig + 4][cn + gid];
        }
        #pragma unroll
        for (int mi = 0; mi < 4; mi++)
            #pragma unroll
            for (int ni = 0; ni < 4; ni++) {
                mma16(acc[mi][ni], afh[mi], bfh[ni]);
                mma16(acc[mi][ni], afh[mi], bfl[ni]);
                mma16(acc[mi][ni], afl[mi], bfh[ni]);
            }
    }

    float*    Cp  = C  ? C  + bo * cO + bi * cI : (float*)0;
    uint32_t* Chp = Ch ? Ch + bo * cO + bi * cI : (uint32_t*)0;
    uint32_t* Clp = Cl ? Cl + bo * cO + bi * cI : (uint32_t*)0;

    #pragma unroll
    for (int mi = 0; mi < 4; mi++) {
        int r0 = rowBase + wm * 64 + mi * 16 + gid;
        int r1 = r0 + 8;
        #pragma unroll
        for (int ni = 0; ni < 4; ni++) {
            int c0 = colBase + wn * 32 + ni * 8 + tig * 2;
            int c1 = c0 + 1;
            float b0 = bias ? biasAlpha * bias[(c0 < N) ? c0 : 0] : 0.f;
            float b1 = bias ? biasAlpha * bias[(c1 < N) ? c1 : 0] : 0.f;
            if (Cp) {
                if (r0 < M && c0 < N) Cp[(long)r0 * ldc + c0] = alpha * acc[mi][ni][0] + b0;
                if (r0 < M && c1 < N) Cp[(long)r0 * ldc + c1] = alpha * acc[mi][ni][1] + b1;
                if (r1 < M && c0 < N) Cp[(long)r1 * ldc + c0] = alpha * acc[mi][ni][2] + b0;
                if (r1 < M && c1 < N) Cp[(long)r1 * ldc + c1] = alpha * acc[mi][ni][3] + b1;
            }
            if (Chp && c0 < N) {
                if (r0 < M) {
                    uint32_t lo, hi = pack_hi(alpha * acc[mi][ni][0] + b0,
                                              alpha * acc[mi][ni][1] + b1, lo);
                    Chp[(long)r0 * ldcs + (c0 >> 1)] = hi;
                    Clp[(long)r0 * ldcs + (c0 >> 1)] = lo;
                }
                if (r1 < M) {
                    uint32_t lo, hi = pack_hi(alpha * acc[mi][ni][2] + b0,
                                              alpha * acc[mi][ni][3] + b1, lo);
                    Chp[(long)r1 * ldcs + (c0 >> 1)] = hi;
                    Clp[(long)r1 * ldcs + (c0 >> 1)] = lo;
                }
            }
        }
    }
}

// ---------------- split kernels ----------------
__global__ void splitB_k(const float* __restrict__ src, uint32_t* __restrict__ dh,
                         uint32_t* __restrict__ dl, int Kp, int N, int dstLd,
                         long kStr, long nStr, long srcBOff, long dstBOff, int nBatch)
{
    long idx = (long)blockIdx.x * blockDim.x + threadIdx.x;
    long per = (long)Kp * dstLd;
    if (idx >= per * nBatch) return;
    int b = (int)(idx / per);
    long r = idx % per;
    int kp = (int)(r / dstLd), n = (int)(r % dstLd);
    float v0 = 0.f, v1 = 0.f;
    if (n < N) {
        const float* s = src + (long)b * srcBOff;
        v0 = s[(long)(2 * kp) * kStr + (long)n * nStr];
        v1 = s[(long)(2 * kp + 1) * kStr + (long)n * nStr];
    }
    uint32_t lo, hi = pack_hi(v0, v1, lo);
    dh[(long)b * dstBOff + r] = hi;
    dl[(long)b * dstBOff + r] = lo;
}

// A-format split (k contiguous): dst[m][kp]
__global__ void splitA_k(const float* __restrict__ src, uint32_t* __restrict__ dh,
                         uint32_t* __restrict__ dl, int M, int Kp, int lda)
{
    long idx = (long)blockIdx.x * blockDim.x + threadIdx.x;
    if (idx >= (long)M * Kp) return;
    int m = (int)(idx / Kp), kp = (int)(idx % Kp);
    float v0 = src[(long)m * lda + 2 * kp];
    float v1 = src[(long)m * lda + 2 * kp + 1];
    uint32_t lo, hi = pack_hi(v0, v1, lo);
    dh[idx] = hi; dl[idx] = lo;
}

// rkT split, tiled transpose, batched over layers via blockIdx.z
__global__ void rkTsplit_k(const float* __restrict__ rk, uint32_t* __restrict__ dh,
                           uint32_t* __restrict__ dl)
{
    int l = blockIdx.z;
    rk += (long)l * 1024 * 1024;
    dh += (long)l * 1024 * 512;
    dl += (long)l * 1024 * 512;
    __shared__ float ts[64][33];
    int nhBase = blockIdx.x * 32;
    int dBase  = blockIdx.y * 64;
    int tx = threadIdx.x, ty = threadIdx.y;   // 32 x 8
    #pragma unroll
    for (int dl_ = ty; dl_ < 64; dl_ += 8)
        ts[dl_][tx] = rk[(long)(dBase + dl_) * 1024 + nhBase + tx];
    __syncthreads();
    #pragma unroll
    for (int nl = ty; nl < 32; nl += 8) {
        uint32_t lo, hi = pack_hi(ts[2 * tx][nl], ts[2 * tx + 1][nl], lo);
        long o = (long)(nhBase + nl) * 512 + (dBase >> 1) + tx;
        dh[o] = hi; dl[o] = lo;
    }
}

// k split + bias, tiled transpose
__global__ void ksplit_k(const float* __restrict__ k, const float* __restrict__ bk,
                         uint32_t* __restrict__ dh, uint32_t* __restrict__ dl, int Lk)
{
    __shared__ float ts[32][65];
    int jBase = blockIdx.x * 32;
    int dBase = blockIdx.y * 64;
    int b = blockIdx.z;
    long per = (long)512 * Lk;
    const float* kb = k + (long)b * Lk * DMODEL;
    int tx = threadIdx.x, ty = threadIdx.y;   // 32 x 8
    #pragma unroll
    for (int jl = ty; jl < 32; jl += 8) {
        ts[jl][tx]      = kb[(long)(jBase + jl) * DMODEL + dBase + tx];
        ts[jl][tx + 32] = kb[(long)(jBase + jl) * DMODEL + dBase + tx + 32];
    }
    __syncthreads();
    #pragma unroll
    for (int dpl = ty; dpl < 32; dpl += 8) {
        float b0 = bk[dBase + 2 * dpl], b1 = bk[dBase + 2 * dpl + 1];
        uint32_t lo, hi = pack_hi(ts[tx][2 * dpl] + b0, ts[tx][2 * dpl + 1] + b1, lo);
        long o = (long)b * per + (long)((dBase >> 1) + dpl) * Lk + jBase + tx;
        dh[o] = hi; dl[o] = lo;
    }
}

// v split + bias
__global__ void vsplit_k(const float* __restrict__ v, const float* __restrict__ bv,
                         uint32_t* __restrict__ dh, uint32_t* __restrict__ dl, int Lk)
{
    long idx = (long)blockIdx.x * blockDim.x + threadIdx.x;
    long per = (long)(Lk / 2) * DMODEL;
    if (idx >= 2 * per) return;
    int b = (int)(idx / per);
    long r = idx % per;
    int jp = (int)(r / DMODEL), d = (int)(r % DMODEL);
    float bb = bv[d];
    float v0 = v[((long)b * Lk + 2 * jp) * DMODEL + d] + bb;
    float v1 = v[((long)b * Lk + 2 * jp + 1) * DMODEL + d] + bb;
    uint32_t lo, hi = pack_hi(v0, v1, lo);
    dh[(long)b * per + r] = hi;
    dl[(long)b * per + r] = lo;
}

// ---------------- fused q-prep: addbias2s + ttb (both read q only; no smem) ----
__global__ void qprep_k(const float* __restrict__ q, const float* __restrict__ bq,
                        const float* __restrict__ rw, const float* __restrict__ rr,
                        const float* __restrict__ rs, const float* __restrict__ seg,
                        uint32_t* __restrict__ qwh, uint32_t* __restrict__ qwl,
                        uint32_t* __restrict__ qqh, uint32_t* __restrict__ qql,
                        float* __restrict__ tt0, float* __restrict__ dtt,
                        int Lq, int nA)
{
    int bid = blockIdx.x;
    int tid = threadIdx.x;
    if (bid < nA) {
        // addbias2s: qw/qq split
        long idx = (long)bid * 256 + tid;
        long total = (long)BATCH * Lq * 512;
        if (idx < total) {
            long row = idx / 512;
            int d2 = (int)(idx % 512);
            int d0 = 2 * d2, d1 = d0 + 1;
            float q0 = q[row * 1024 + d0] + bq[d0], q1 = q[row * 1024 + d1] + bq[d1];
            uint32_t lo, hi;
            hi = pack_hi(QSCALE * (q0 + rw[d0]), QSCALE * (q1 + rw[d1]), lo);
            qwh[idx] = hi; qwl[idx] = lo;
            hi = pack_hi(QSCALE * (q0 + rr[d0]), QSCALE * (q1 + rr[d1]), lo);
            qqh[idx] = hi; qql[idx] = lo;
        }
    } else {
        // ttb: token-type biases
        int idx = (bid - nA) * 256 + tid;
        if (idx < BATCH * NHEADS * Lq) {
            int i = idx % Lq; int bn = idx / Lq; int n = bn % NHEADS; int b = bn / NHEADS;
            const float* qp  = q + ((long)(b * Lq + i)) * DMODEL + n * DHEAD;
            const float* bqp = bq + n * DHEAD;
            const float* rsp = rs + n * DHEAD;
            const float* s0  = seg + n * DHEAD;
            const float* s1  = seg + DMODEL + n * DHEAD;
            float t0 = 0.f, t1 = 0.f;
            #pragma unroll 8
            for (int h = 0; h < DHEAD; h++) {
                float vq = QSCALE * (qp[h] + bqp[h] + rsp[h]);
                t0 += vq * s0[h];
                t1 += vq * s1[h];
            }
            tt0[(long)bn * Lq + i] = t0;
            dtt[(long)bn * Lq + i] = t1 - t0;
        }
    }
}

// ---------------- relative-position basis, generated directly in split form ----
__global__ void relmat_split_k(uint32_t* __restrict__ dh, uint32_t* __restrict__ dl,
                               int nU, int nUp, int g, int d0)
{
    long idx = (long)blockIdx.x * blockDim.x + threadIdx.x;
    long tot = (long)512 * nUp;
    if (idx >= tot) return;
    int kp = (int)(idx / nUp), u = (int)(idx % nUp);
    float v0 = 0.f, v1 = 0.f;
    if (u < nU) {
        int da = 2 * kp, db_ = 2 * kp + 1;
        int fa = (da < 512) ? da : da - 512;
        int fb = (db_ < 512) ? db_ : db_ - 512;
        float invfa = expf(-(float)fa * (9.210340371976184f / 512.0f));
        float invfb = expf(-(float)fb * (9.210340371976184f / 512.0f));
        float base = (float)(g * u + d0);
        float aa = base * invfa, ab = base * invfb;
        v0 = (da < 512) ? sinf(aa) : cosf(aa);
        v1 = (db_ < 512) ? sinf(ab) : cosf(ab);
    }
    uint32_t lo, hi = pack_hi(v0, v1, lo);
    dh[idx] = hi; dl[idx] = lo;
}

// assemble scores (content + rel-pos gather + token-type) and softmax; split probs out
__global__ void softmax_k(const float* __restrict__ S, const float* __restrict__ P,
                          uint32_t* __restrict__ Sh, uint32_t* __restrict__ Sl,
                          const float* __restrict__ tt0, const float* __restrict__ dtt,
                          const int* __restrict__ ids,
                          int Lq, int Lk, int nU, int cq, int ck, int u0, int pq, int pk)
{
    int i = blockIdx.x, n = blockIdx.y, b = blockIdx.z;
    int bn = b * NHEADS + n;
    const float* Srow = S + ((long)bn * Lq + i) * Lk;
    const float* Prow = P + ((long)bn * Lq + i) * nU;
    float t0 = tt0[(long)bn * Lq + i], dt = dtt[(long)bn * Lq + i];
    const int* idk = ids + b * 1024;
    int idq = idk[pq * i];
    int ubase = cq * i + u0;

    __shared__ float sh[MAXTOK];
    __shared__ float red[32];
    int tid = threadIdx.x;

    float lmax = -1e30f;
    for (int j = tid; j < Lk; j += blockDim.x) {
        float tok = (idk[pk * j] == idq) ? (t0 + dt) : t0;
        float v = Srow[j] + Prow[ubase + ck * j] + tok;
        sh[j] = v;
        lmax = fmaxf(lmax, v);
    }
    float bmax = blockReduceMax(lmax, red);

    float lsum = 0.f;
    for (int j = tid; j < Lk; j += blockDim.x) {
        float e = expf(sh[j] - bmax);
        sh[j] = e;
        lsum += e;
    }
    float bsum = blockReduceSum(lsum, red);
    float inv = 1.0f / bsum;

    long srow = ((long)bn * Lq + i) * (Lk >> 1);
    for (int j2 = tid; j2 < (Lk >> 1); j2 += blockDim.x) {
        uint32_t lo, hi = pack_hi(sh[2 * j2] * inv, sh[2 * j2 + 1] * inv, lo);
        Sh[srow + j2] = hi;
        Sl[srow + j2] = lo;
    }
}

// residual + LayerNorm; writes float out + split out
__global__ void ln_k(const float* __restrict__ qin, const float* __restrict__ tmp,
                     const float* __restrict__ gvec, const float* __restrict__ bvec,
                     float* __restrict__ out, uint32_t* __restrict__ oh,
                     uint32_t* __restrict__ ol)
{
    int r = blockIdx.x, tid = threadIdx.x;
    const float* x1 = qin + (long)r * DMODEL;
    const float* x2 = tmp + (long)r * DMODEL;
    __shared__ float red[32];
    float s = 0.f;
    for (int d = tid; d < DMODEL; d += blockDim.x) s += x1[d] + x2[d];
    float mu = blockReduceSum(s, red) * (1.0f / DMODEL);
    float vs = 0.f;
    for (int d = tid; d < DMODEL; d += blockDim.x) {
        float z = x1[d] + x2[d] - mu;
        vs += z * z;
    }
    float var = blockReduceSum(vs, red) * (1.0f / DMODEL);
    float rstd = rsqrtf(var + LNEPS);
    for (int d2 = tid; d2 < 512; d2 += blockDim.x) {
        int d0 = 2 * d2, d1 = d0 + 1;
        float o0 = (x1[d0] + x2[d0] - mu) * rstd * gvec[d0] + bvec[d0];
        float o1 = (x1[d1] + x2[d1] - mu) * rstd * gvec[d1] + bvec[d1];
        out[(long)r * DMODEL + d0] = o0;
        out[(long)r * DMODEL + d1] = o1;
        uint32_t lo, hi = pack_hi(o0, o1, lo);
        oh[(long)r * 512 + d2] = hi;
        ol[(long)r * 512 + d2] = lo;
    }
}

// upsample; writes float out + split out
__global__ void upsample_k(const float* __restrict__ h, float* __restrict__ out,
                           uint32_t* __restrict__ oh, uint32_t* __restrict__ ol, int Lin)
{
    long idx = (long)blockIdx.x * blockDim.x + threadIdx.x;
    long total = (long)BATCH * Lin * 512;
    if (idx >= total) return;
    int d2 = (int)(idx % 512);
    long bt = idx / 512;
    int t = (int)(bt % Lin);
    int b = (int)(bt / Lin);
    int tp = (t == 0) ? Lin - 1 : t - 1;
    const float* cr = h + ((long)b * Lin + t) * DMODEL + 2 * d2;
    const float* pr = h + ((long)b * Lin + tp) * DMODEL + 2 * d2;
    float c0 = cr[0], c1 = cr[1];
    float i0 = 0.5f * (c0 + pr[0]), i1 = 0.5f * (c1 + pr[1]);
    long r = (long)b * (2 * Lin) + 2 * t;
    out[r * DMODEL + 2 * d2]     = c0;
    out[r * DMODEL + 2 * d2 + 1] = c1;
    out[(r + 1) * DMODEL + 2 * d2]     = i0;
    out[(r + 1) * DMODEL + 2 * d2 + 1] = i1;
    uint32_t lo, hi = pack_hi(c0, c1, lo);
    oh[r * 512 + d2] = hi; ol[r * 512 + d2] = lo;
    hi = pack_hi(i0, i1, lo);
    oh[(r + 1) * 512 + d2] = hi; ol[(r + 1) * 512 + d2] = lo;
}

// ---------------- host ----------------
static void gemmS(const uint32_t* Ah, const uint32_t* Al,
                  const uint32_t* Bh, const uint32_t* Bl,
                  const float* bias, float* C, uint32_t* Ch, uint32_t* Cl,
                  int M, int N, int Kp, int ldau, int ldbu, int ldc, int ldcs,
                  long aO, long aI, long bO, long bI, long cO, long cI,
                  int innerCount, int batches, float alpha, float biasAlpha,
                  int posWin = 0, int pcq = 0, int pck = 0, int pu0 = 0, int pLk = 0)
{
    dim3 grid((N + 127) / 128, (M + 127) / 128, batches);
    gemm_tcs<<<grid, 256>>>(Ah, Al, Bh, Bl, bias, C, Ch, Cl,
                            M, N, Kp, ldau, ldbu, ldc, ldcs,
                            aO, aI, bO, bI, cO, cI, innerCount, alpha, biasAlpha,
                            posWin, pcq, pck, pu0, pLk);
}

static long relSoff(int l) {
    if (l <= 4) return (long)l * S1;
    if (l <= 8) return 5 * S1 + (long)(l - 5) * S2;
    return 5 * S1 + 4 * S2 + (long)(l - 9) * S3;
}

#define GS(sym, var) cudaGetSymbolAddress((void**)&var, sym)

extern "C" void kernel_launch(void* const* d_in, const int* in_sizes, int n_in,
                              void* d_out, int out_size)
{
    const float* final_hidden = (const float*)d_in[0];
    const int*   tok_ids      = (const int*)d_in[5];
    const float* Wq = (const float*)d_in[6];
    const float* bq = (const float*)d_in[7];
    const float* Wk = (const float*)d_in[8];
    const float* bk = (const float*)d_in[9];
    const float* Wv = (const float*)d_in[10];
    const float* bv = (const float*)d_in[11];
    const float* rw = (const float*)d_in[12];
    const float* rr = (const float*)d_in[13];
    const float* rs = (const float*)d_in[14];
    const float* rk = (const float*)d_in[15];
    const float* sg = (const float*)d_in[16];
    const float* Wp = (const float*)d_in[17];
    const float* bp = (const float*)d_in[18];
    const float* lg = (const float*)d_in[19];
    const float* lb = (const float*)d_in[20];
    float* out = (float*)d_out;

    float *p_qkv,*p_tmp,*p_hA,*p_hB,*p_up,*p_S,*p_P,*p_RELF,*p_t0,*p_dt;
    GS(g_qkv,p_qkv); GS(g_tmp,p_tmp);
    GS(g_hA,p_hA); GS(g_hB,p_hB); GS(g_up,p_up);
    GS(g_S,p_S); GS(g_P,p_P); GS(g_RELF,p_RELF);
    GS(g_tt0,p_t0); GS(g_dtt,p_dt);

    uint32_t *wch,*wcl,*wph,*wpl;
    uint32_t *r1h,*r1l,*r2h,*r2l,*r3h,*r3l,*rkth,*rktl,*relh,*rell;
    uint32_t *ksh,*ksl,*vsh,*vsl,*qwh,*qwl,*qqh,*qql,*ssh,*ssl,*vch,*vcl,*hsh,*hsl,*ush,*usl;
    GS(g_Wch,wch); GS(g_Wcl,wcl); GS(g_Wph,wph); GS(g_Wpl,wpl);
    GS(g_R1h,r1h); GS(g_R1l,r1l); GS(g_R2h,r2h); GS(g_R2l,r2l); GS(g_R3h,r3h); GS(g_R3l,r3l);
    GS(g_rkTh,rkth); GS(g_rkTl,rktl); GS(g_RELh,relh); GS(g_RELl,rell);
    GS(g_ksh,ksh); GS(g_ksl,ksl); GS(g_vsh,vsh); GS(g_vsl,vsl);
    GS(g_qwh,qwh); GS(g_qwl,qwl); GS(g_qqh,qqh); GS(g_qql,qql);
    GS(g_Ssh,ssh); GS(g_Ssl,ssl); GS(g_vch,vch); GS(g_vcl,vcl);
    GS(g_hsh,hsh); GS(g_hsl,hsl); GS(g_ush,ush); GS(g_usl,usl);

    // ---- setup: rel-pos bases + weight splits ----
    relmat_split_k<<<(512*NUP1 + 255)/256, 256>>>(r1h, r1l, NU1, NUP1, 1, -1023);
    relmat_split_k<<<(512*1024 + 255)/256, 256>>>(r2h, r2l, NU2, 1024, 2, -1022);
    relmat_split_k<<<(512*512  + 255)/256, 256>>>(r3h, r3l, NU3, 512,  4, -1020);
    {
        long t = (long)6144*1024;
        splitB_k<<<(unsigned)((t+255)/256),256>>>(Wq, wch,          wcl,          6144, 1024, 1024, 1024, 1, 0, 0, 1);
        splitB_k<<<(unsigned)((t+255)/256),256>>>(Wk, wch + WSPL,   wcl + WSPL,   6144, 1024, 1024, 1024, 1, 0, 0, 1);
        splitB_k<<<(unsigned)((t+255)/256),256>>>(Wv, wch + 2*WSPL, wcl + 2*WSPL, 6144, 1024, 1024, 1024, 1, 0, 0, 1);
        splitB_k<<<(unsigned)((t+255)/256),256>>>(Wp, wph, wpl, 6144, 1024, 1024, 1024, 1, 0, 0, 1);
        t = (long)512*512;  splitA_k<<<(unsigned)((t+255)/256),256>>>(final_hidden, hsh, hsl, 512, 512, 1024);
    }

    // ---- hoisted REL pipeline: all 12 layers, batched by R-group ----
    {
        dim3 tb(32, 8), tg(32, 16, 12);
        rkTsplit_k<<<tg, tb>>>(rk, rkth, rktl);
    }
    gemmS(rkth, rktl, r1h, r1l, nullptr, p_RELF, nullptr, nullptr,
          1024, NU1, 512, 512, NUP1, NU1, 0,
          0, (long)1024*512, 0, 0, 0, F1,
          5, 5, 1.f, 0.f);
    gemmS(rkth + (long)5*1024*512, rktl + (long)5*1024*512, r2h, r2l, nullptr,
          p_RELF + 5*F1, nullptr, nullptr,
          1024, NU2, 512, 512, 1024, NU2, 0,
          0, (long)1024*512, 0, 0, 0, F2,
          4, 4, 1.f, 0.f);
    gemmS(rkth + (long)9*1024*512, rktl + (long)9*1024*512, r3h, r3l, nullptr,
          p_RELF + 5*F1 + 4*F2, nullptr, nullptr,
          1024, NU3, 512, 512, 512, NU3, 0,
          0, (long)1024*512, 0, 0, 0, F3,
          3, 3, 1.f, 0.f);
    {
        long t;
        t = (long)80*32*NUP1;
        splitB_k<<<(unsigned)((t+255)/256),256>>>(p_RELF, relh, rell, 32, NU1, NUP1,
                                                  NU1, 1, (long)64*NU1, (long)32*NUP1, 80);
        t = (long)64*32*1024;
        splitB_k<<<(unsigned)((t+255)/256),256>>>(p_RELF + 5*F1, relh + 5*S1, rell + 5*S1,
                                                  32, NU2, 1024, NU2, 1, (long)64*NU2, (long)32*1024, 64);
        t = (long)48*32*512;
        splitB_k<<<(unsigned)((t+255)/256),256>>>(p_RELF + 5*F1 + 4*F2, relh + 5*S1 + 4*S2,
                                                  rell + 5*S1 + 4*S2,
                                                  32, NU3, 512, NU3, 1, (long)64*NU3, (long)32*512, 48);
    }

    const float* hidden = final_hidden;
    float* bufs[2] = {p_hA, p_hB};
    int pb = 0;

    for (int l = 11; l >= 0; --l) {
        int Lq, Lk, do_up, nU, nUp, cq, ck, u0, pq, pk;
        if (l <= 3)      { Lq=1024; Lk=1024; do_up=0; nU=NU1; nUp=NUP1; cq= 1; ck=-1; u0=1023; pq=1; pk=1; }
        else if (l == 4) { Lq=1024; Lk=512;  do_up=1; nU=NU1; nUp=NUP1; cq=-1; ck= 2; u0=1023; pq=1; pk=2; }
        else if (l <= 7) { Lq=512;  Lk=512;  do_up=0; nU=NU2; nUp=1024; cq= 1; ck=-1; u0=511;  pq=2; pk=2; }
        else if (l == 8) { Lq=512;  Lk=256;  do_up=1; nU=NU2; nUp=1024; cq=-1; ck= 2; u0=511;  pq=2; pk=4; }
        else             { Lq=256;  Lk=256;  do_up=0; nU=NU3; nUp=512;  cq= 1; ck=-1; u0=255;  pq=4; pk=4; }

        if (l == 11) { long t = (long)BATCH*256*512; upsample_k<<<(unsigned)((t+255)/256),256>>>(hidden, p_up, ush, usl, 256); }
        if (l == 7)  { long t = (long)BATCH*512*512; upsample_k<<<(unsigned)((t+255)/256),256>>>(hidden, p_up, ush, usl, 512); }

        const float* q_in_f = do_up ? p_up : hidden;
        uint32_t* qinh = do_up ? ush : hsh;
        uint32_t* qinl = do_up ? usl : hsl;
        uint32_t* relh_l = relh + relSoff(l);
        uint32_t* rell_l = rell + relSoff(l);

        float* p_q = p_qkv;
        float* p_k = p_qkv + QKVSTR;
        float* p_v = p_qkv + 2 * QKVSTR;

        // merged QKV projections (no bias; folded downstream)
        long WO = (long)WSPL;
        if (do_up) {
            gemmS(qinh, qinl, wch + (long)l*512*1024, wcl + (long)l*512*1024, nullptr,
                  p_q, nullptr, nullptr,
                  BATCH*Lq, DMODEL, 512, 512, 1024, DMODEL, 0,
                  0,0,0,0,0,0, 1, 1, 1.f, 0.f);
            gemmS(hsh, hsl, wch + WO + (long)l*512*1024, wcl + WO + (long)l*512*1024, nullptr,
                  p_k, nullptr, nullptr,
                  BATCH*Lk, DMODEL, 512, 512, 1024, DMODEL, 0,
                  0, 0, WO, 0, QKVSTR, 0,
                  1, 2, 1.f, 0.f);
        } else {
            gemmS(hsh, hsl, wch + (long)l*512*1024, wcl + (long)l*512*1024, nullptr,
                  p_q, nullptr, nullptr,
                  BATCH*Lq, DMODEL, 512, 512, 1024, DMODEL, 0,
                  0, 0, WO, 0, QKVSTR, 0,
                  1, 3, 1.f, 0.f);
        }

        // k/v splits (+bias); k via tiled transpose (separate, as in R14)
        {
            dim3 tb(32, 8), tg(Lk / 32, 16, 2);
            ksplit_k<<<tg, tb>>>(p_k, bk + l*DMODEL, ksh, ksl, Lk);
            long t = (long)2*(Lk/2)*DMODEL;
            vsplit_k<<<(unsigned)((t+255)/256),256>>>(p_v, bv + l*DMODEL, vsh, vsl, Lk);
        }
        // fused q-prep: addbias2s + ttb in ONE homogeneous launch
        {
            int nA  = 4 * Lq;              // BATCH*Lq*512 / 256
            int tot = nA + Lq / 8;         // + BATCH*NHEADS*Lq / 256
            qprep_k<<<tot, 256>>>(p_q, bq + l*DMODEL, rw + l*DMODEL, rr + l*DMODEL,
                                  rs + l*DMODEL, sg + (long)l*2*DMODEL,
                                  qwh, qwl, qqh, qql, p_t0, p_dt, Lq, nA);
        }

        // content scores -> S
        gemmS(qwh, qwl, ksh, ksl, nullptr, p_S, nullptr, nullptr,
              Lq, Lk, 32, 512, Lk, Lk, 0,
              (long)Lq*512, 32, (long)512*Lk, (long)32*Lk,
              (long)NHEADS*Lq*Lk, (long)Lq*Lk,
              NHEADS, BATCH*NHEADS, 1.f, 0.f);

        // P (rel-pos projections), window-culled
        gemmS(qqh, qql, relh_l, rell_l, nullptr, p_P, nullptr, nullptr,
              Lq, nU, 32, 512, nUp, nU, 0,
              (long)Lq*512, 32, 0, (long)32*nUp,
              (long)NHEADS*Lq*nU, (long)Lq*nU,
              NHEADS, BATCH*NHEADS, 1.f, 0.f,
              1, cq, ck, u0, Lk);

        // softmax (gathers P band, writes split probs)
        {
            dim3 grid(Lq, NHEADS, BATCH);
            softmax_k<<<grid, 256>>>(p_S, p_P, ssh, ssl, p_t0, p_dt, tok_ids,
                                     Lq, Lk, nU, cq, ck, u0, pq, pk);
        }

        // vec = prob @ v (split output)
        gemmS(ssh, ssl, vsh, vsl, nullptr, nullptr, vch, vcl,
              Lq, DHEAD, Lk/2, Lk/2, DMODEL, 0, 512,
              (long)NHEADS*Lq*(Lk/2), (long)Lq*(Lk/2),
              (long)(Lk/2)*DMODEL, 64,
              (long)Lq*512, 32,
              NHEADS, BATCH*NHEADS, 1.f, 0.f);

        // post projection
        gemmS(vch, vcl, wph + (long)l*512*1024, wpl + (long)l*512*1024, bp + l*DMODEL,
              p_tmp, nullptr, nullptr,
              BATCH*Lq, DMODEL, 512, 512, 1024, DMODEL, 0,
              0,0,0,0,0,0, 1, 1, 1.f, 1.f);

        // residual + LayerNorm (writes float hidden + split hidden)
        float* dst = (l == 0) ? out : bufs[pb];
        ln_k<<<BATCH*Lq, 256>>>(q_in_f, p_tmp, lg + l*DMODEL, lb + l*DMODEL, dst, hsh, hsl);

        hidden = dst;
        pb ^= 1;
    }
}

// round 17
// speedup vs baseline: 1.0346x; 1.0253x over previous
#include <cuda_runtime.h>
#include <cuda_bf16.h>
#include <math.h>
#include <stdint.h>

#define NHEADS 16
#define DHEAD  64
#define DMODEL 1024
#define BATCH  2
#define QSCALE 0.125f
#define MAXTOK 1024
#define NU1 2047
#define NU2 1023
#define NU3 511
#define NUP1 2048
#define LNEPS 1e-9f
#define SLACK 4096
#define QKVSTR ((long)BATCH*MAXTOK*DMODEL)

// per-layer REL strides (float buffer and split buffer)
#define F1 ((long)16*64*NU1)
#define F2 ((long)16*64*NU2)
#define F3 ((long)16*64*NU3)
#define S1 ((long)16*32*NUP1)
#define S2 ((long)16*32*1024)
#define S3 ((long)16*32*512)

// ---------------- float scratch ----------------
__device__ float g_qkv[3*BATCH*MAXTOK*DMODEL];
__device__ float g_tmp[BATCH*MAXTOK*DMODEL];
__device__ float g_hA [BATCH*MAXTOK*DMODEL];
__device__ float g_hB [BATCH*MAXTOK*DMODEL];
__device__ float g_up [BATCH*MAXTOK*DMODEL];
__device__ float g_S  [(size_t)BATCH*NHEADS*MAXTOK*MAXTOK];
__device__ float g_P  [(size_t)BATCH*NHEADS*MAXTOK*NU1];
__device__ float g_RELF[16240640 + SLACK];   // 5*F1 + 4*F2 + 3*F3
__device__ float g_tt0[BATCH*NHEADS*MAXTOK];
__device__ float g_dtt[BATCH*NHEADS*MAXTOK];

// ---------------- split scratch (u32 = packed bf16 pair along k) ----------------
#define WSPL (12*512*1024)
__device__ __align__(16) uint32_t g_Wch[3*WSPL+SLACK], g_Wcl[3*WSPL+SLACK];
__device__ __align__(16) uint32_t g_Wph[WSPL+SLACK], g_Wpl[WSPL+SLACK];
__device__ __align__(16) uint32_t g_R1h[512*NUP1+SLACK], g_R1l[512*NUP1+SLACK];
__device__ __align__(16) uint32_t g_R2h[512*1024+SLACK], g_R2l[512*1024+SLACK];
__device__ __align__(16) uint32_t g_R3h[512*512+SLACK],  g_R3l[512*512+SLACK];
__device__ __align__(16) uint32_t g_rkTh[12*1024*512+SLACK], g_rkTl[12*1024*512+SLACK];
__device__ __align__(16) uint32_t g_RELh[8126464+SLACK], g_RELl[8126464+SLACK]; // 5*S1+4*S2+3*S3
__device__ __align__(16) uint32_t g_ksh[2*512*1024+SLACK], g_ksl[2*512*1024+SLACK];
__device__ __align__(16) uint32_t g_vsh[2*512*1024+SLACK], g_vsl[2*512*1024+SLACK];
__device__ __align__(16) uint32_t g_qwh[BATCH*MAXTOK*512+SLACK], g_qwl[BATCH*MAXTOK*512+SLACK];
__device__ __align__(16) uint32_t g_qqh[BATCH*MAXTOK*512+SLACK], g_qql[BATCH*MAXTOK*512+SLACK];
__device__ __align__(16) uint32_t g_Ssh[(size_t)BATCH*NHEADS*MAXTOK*512+SLACK];
__device__ __align__(16) uint32_t g_Ssl[(size_t)BATCH*NHEADS*MAXTOK*512+SLACK];
__device__ __align__(16) uint32_t g_vch[BATCH*MAXTOK*512+SLACK], g_vcl[BATCH*MAXTOK*512+SLACK];
__device__ __align__(16) uint32_t g_hsh[BATCH*MAXTOK*512+SLACK], g_hsl[BATCH*MAXTOK*512+SLACK];
__device__ __align__(16) uint32_t g_ush[BATCH*MAXTOK*512+SLACK], g_usl[BATCH*MAXTOK*512+SLACK];

// ---------------- helpers ----------------
__device__ __forceinline__ uint32_t pack_hi(float x0, float x1, uint32_t& lo) {
    __nv_bfloat16 h0 = __float2bfloat16_rn(x0);
    __nv_bfloat16 h1 = __float2bfloat16_rn(x1);
    float r0 = x0 - __bfloat162float(h0);
    float r1 = x1 - __bfloat162float(h1);
    __nv_bfloat162 hp; hp.x = h0; hp.y = h1;
    __nv_bfloat162 lp = __floats2bfloat162_rn(r0, r1);
    lo = *reinterpret_cast<uint32_t*>(&lp);
    return *reinterpret_cast<uint32_t*>(&hp);
}

__device__ __forceinline__ void mma16(float c[4], const uint32_t a[4], const uint32_t b[2]) {
    asm volatile(
        "mma.sync.aligned.m16n8k16.row.col.f32.bf16.bf16.f32 "
        "{%0,%1,%2,%3}, {%4,%5,%6,%7}, {%8,%9}, {%0,%1,%2,%3};"
        : "+f"(c[0]), "+f"(c[1]), "+f"(c[2]), "+f"(c[3])
        : "r"(a[0]), "r"(a[1]), "r"(a[2]), "r"(a[3]), "r"(b[0]), "r"(b[1]));
}

__device__ __forceinline__ float blockReduceSum(float v, float* red) {
    __syncthreads();
    #pragma unroll
    for (int o = 16; o > 0; o >>= 1) v += __shfl_down_sync(0xffffffffu, v, o);
    int lane = threadIdx.x & 31, w = threadIdx.x >> 5;
    if (lane == 0) red[w] = v;
    __syncthreads();
    int nw = (blockDim.x + 31) >> 5;
    if (w == 0) {
        v = (lane < nw) ? red[lane] : 0.f;
        #pragma unroll
        for (int o = 16; o > 0; o >>= 1) v += __shfl_down_sync(0xffffffffu, v, o);
        if (lane == 0) red[0] = v;
    }
    __syncthreads();
    return red[0];
}
__device__ __forceinline__ float blockReduceMax(float v, float* red) {
    __syncthreads();
    #pragma unroll
    for (int o = 16; o > 0; o >>= 1) v = fmaxf(v, __shfl_down_sync(0xffffffffu, v, o));
    int lane = threadIdx.x & 31, w = threadIdx.x >> 5;
    if (lane == 0) red[w] = v;
    __syncthreads();
    int nw = (blockDim.x + 31) >> 5;
    if (w == 0) {
        v = (lane < nw) ? red[lane] : -1e30f;
        #pragma unroll
        for (int o = 16; o > 0; o >>= 1) v = fmaxf(v, __shfl_down_sync(0xffffffffu, v, o));
        if (lane == 0) red[0] = v;
    }
    __syncthreads();
    return red[0];
}

// ---------------- unified split-input tensor-core GEMM (3xBF16) ----------------
#define ASTR 12
#define TSTR 136

__global__ __launch_bounds__(256, 2)
void gemm_tcs(const uint32_t* __restrict__ Ah_, const uint32_t* __restrict__ Al_,
              const uint32_t* __restrict__ Bh_, const uint32_t* __restrict__ Bl_,
              const float* __restrict__ bias, float* __restrict__ C,
              uint32_t* __restrict__ Ch, uint32_t* __restrict__ Cl,
              int M, int N, int Kp, int ldau, int ldbu, int ldc, int ldcs,
              long aO, long aI, long bO, long bI, long cO, long cI,
              int innerCount, float alpha, float biasAlpha,
              int posWin, int pcq, int pck, int pu0, int pLk)
{
    int rowBase = blockIdx.y * 128;
    int colBase = blockIdx.x * 128;
    if (posWin) {
        int r0 = rowBase, r1 = min(rowBase + 127, M - 1);
        int t1 = pcq * r0, t2 = pcq * r1;
        int umin = pu0 + min(t1, t2) + min(0, pck * (pLk - 1));
        int umax = pu0 + max(t1, t2) + max(0, pck * (pLk - 1));
        if (colBase > umax || colBase + 127 < umin) return;
    }
    int bz = blockIdx.z;
    int bo = bz / innerCount, bi = bz % innerCount;
    const uint32_t* Ahp = Ah_ + bo * aO + bi * aI;
    const uint32_t* Alp = Al_ + bo * aO + bi * aI;
    const uint32_t* Bhp = Bh_ + bo * bO + bi * bI;
    const uint32_t* Blp = Bl_ + bo * bO + bi * bI;

    __shared__ uint32_t Ash[128][ASTR], Asl[128][ASTR];
    __shared__ uint32_t Bsh[8][TSTR],  Bsl[8][TSTR];

    int tid = threadIdx.x, lane = tid & 31, warp = tid >> 5;
    int wm = warp & 1, wn = warp >> 1;
    int gid = lane >> 2, tig = lane & 3;

    int rowA = tid >> 1, halfA = (tid & 1) * 4;
    int kpB  = tid >> 5, nB = (tid & 31) * 4;
    bool aOk = (rowBase + rowA) < M;
    long aBase = (long)(rowBase + rowA) * ldau + halfA;
    long bBase = (long)kpB * ldbu + colBase + nB;

    // ldmatrix addresses for A fragments (loop-invariant)
    int arow = (lane < 16) ? lane : (lane - 16);
    int acol = (lane < 16) ? 0 : 4;
    uint32_t aAddrH[4], aAddrL[4];
    #pragma unroll
    for (int mi = 0; mi < 4; mi++) {
        int rm = wm * 64 + mi * 16;
        aAddrH[mi] = (uint32_t)__cvta_generic_to_shared(&Ash[rm + arow][acol]);
        aAddrL[mi] = (uint32_t)__cvta_generic_to_shared(&Asl[rm + arow][acol]);
    }

    float acc[4][4][4];
    #pragma unroll
    for (int a = 0; a < 4; a++)
        #pragma unroll
        for (int b = 0; b < 4; b++)
            #pragma unroll
            for (int c = 0; c < 4; c++) acc[a][b][c] = 0.f;

    uint4 zz = make_uint4(0, 0, 0, 0);
    uint4 ra_h = aOk ? *(const uint4*)(Ahp + aBase) : zz;
    uint4 ra_l = aOk ? *(const uint4*)(Alp + aBase) : zz;
    uint4 rb_h = *(const uint4*)(Bhp + bBase);
    uint4 rb_l = *(const uint4*)(Blp + bBase);

    for (int kp0 = 0; kp0 < Kp; kp0 += 8) {
        __syncthreads();
        *(uint4*)&Ash[rowA][halfA] = ra_h;
        *(uint4*)&Asl[rowA][halfA] = ra_l;
        *(uint4*)&Bsh[kpB][nB]     = rb_h;
        *(uint4*)&Bsl[kpB][nB]     = rb_l;
        __syncthreads();

        int kn = kp0 + 8;
        if (kn < Kp) {
            ra_h = aOk ? *(const uint4*)(Ahp + aBase + kn) : zz;
            ra_l = aOk ? *(const uint4*)(Alp + aBase + kn) : zz;
            rb_h = *(const uint4*)(Bhp + bBase + (long)kn * ldbu);
            rb_l = *(const uint4*)(Blp + bBase + (long)kn * ldbu);
        }

        uint32_t afh[4][4], afl[4][4];
        #pragma unroll
        for (int mi = 0; mi < 4; mi++) {
            asm volatile(
                "ldmatrix.sync.aligned.m8n8.x4.shared.b16 {%0,%1,%2,%3}, [%4];"
                : "=r"(afh[mi][0]), "=r"(afh[mi][1]), "=r"(afh[mi][2]), "=r"(afh[mi][3])
                : "r"(aAddrH[mi]));
            asm volatile(
                "ldmatrix.sync.aligned.m8n8.x4.shared.b16 {%0,%1,%2,%3}, [%4];"
                : "=r"(afl[mi][0]), "=r"(afl[mi][1]), "=r"(afl[mi][2]), "=r"(afl[mi][3])
                : "r"(aAddrL[mi]));
        }
        uint32_t bfh[4][2], bfl[4][2];
        #pragma unroll
        for (int ni = 0; ni < 4; ni++) {
            int cn = wn * 32 + ni * 8;
            bfh[ni][0] = Bsh[tig    ][cn + gid];
            bfh[ni][1] = Bsh[tig + 4][cn + gid];
            bfl[ni][0] = Bsl[tig    ][cn + gid];
            bfl[ni][1] = Bsl[tig + 4][cn + gid];
        }
        #pragma unroll
        for (int mi = 0; mi < 4; mi++)
            #pragma unroll
            for (int ni = 0; ni < 4; ni++) {
                mma16(acc[mi][ni], afh[mi], bfh[ni]);
                mma16(acc[mi][ni], afh[mi], bfl[ni]);
                mma16(acc[mi][ni], afl[mi], bfh[ni]);
            }
    }

    float*    Cp  = C  ? C  + bo * cO + bi * cI : (float*)0;
    uint32_t* Chp = Ch ? Ch + bo * cO + bi * cI : (uint32_t*)0;
    uint32_t* Clp = Cl ? Cl + bo * cO + bi * cI : (uint32_t*)0;

    #pragma unroll
    for (int mi = 0; mi < 4; mi++) {
        int r0 = rowBase + wm * 64 + mi * 16 + gid;
        int r1 = r0 + 8;
        #pragma unroll
        for (int ni = 0; ni < 4; ni++) {
            int c0 = colBase + wn * 32 + ni * 8 + tig * 2;
            int c1 = c0 + 1;
            float b0 = bias ? biasAlpha * bias[(c0 < N) ? c0 : 0] : 0.f;
            float b1 = bias ? biasAlpha * bias[(c1 < N) ? c1 : 0] : 0.f;
            if (Cp) {
                if (r0 < M && c0 < N) Cp[(long)r0 * ldc + c0] = alpha * acc[mi][ni][0] + b0;
                if (r0 < M && c1 < N) Cp[(long)r0 * ldc + c1] = alpha * acc[mi][ni][1] + b1;
                if (r1 < M && c0 < N) Cp[(long)r1 * ldc + c0] = alpha * acc[mi][ni][2] + b0;
                if (r1 < M && c1 < N) Cp[(long)r1 * ldc + c1] = alpha * acc[mi][ni][3] + b1;
            }
            if (Chp && c0 < N) {
                if (r0 < M) {
                    uint32_t lo, hi = pack_hi(alpha * acc[mi][ni][0] + b0,
                                              alpha * acc[mi][ni][1] + b1, lo);
                    Chp[(long)r0 * ldcs + (c0 >> 1)] = hi;
                    Clp[(long)r0 * ldcs + (c0 >> 1)] = lo;
                }
                if (r1 < M) {
                    uint32_t lo, hi = pack_hi(alpha * acc[mi][ni][2] + b0,
                                              alpha * acc[mi][ni][3] + b1, lo);
                    Chp[(long)r1 * ldcs + (c0 >> 1)] = hi;
                    Clp[(long)r1 * ldcs + (c0 >> 1)] = lo;
                }
            }
        }
    }
}

// ---------------- split kernels ----------------
// power-of-2 split: dst[kp][n] (ld = 1<<logLd) = pack(src[2kp*kStr + n], src[(2kp+1)*kStr + n])
// nStr==1 at all call sites; indices via shift/mask (no 64-bit div).
__global__ void splitBP_k(const float* __restrict__ src, uint32_t* __restrict__ dh,
                          uint32_t* __restrict__ dl, int N, int logLd, long kStr,
                          long srcBOff, long dstBOff, int nBatch, int logPer, long total)
{
    long idx = (long)blockIdx.x * blockDim.x + threadIdx.x;
    if (idx >= total) return;
    int b; long r;
    if (nBatch > 1) {
        b = (int)(idx >> logPer);
        r = idx & ((1L << logPer) - 1);
    } else {
        b = 0; r = idx;
    }
    int kp = (int)(r >> logLd);
    int n  = (int)(r & ((1 << logLd) - 1));
    float v0 = 0.f, v1 = 0.f;
    if (n < N) {
        const float* s = src + (long)b * srcBOff + (long)(2 * kp) * kStr + n;
        v0 = s[0];
        v1 = s[kStr];
    }
    uint32_t lo, hi = pack_hi(v0, v1, lo);
    dh[(long)b * dstBOff + r] = hi;
    dl[(long)b * dstBOff + r] = lo;
}

// A-format split (k contiguous): dst[m][kp]
__global__ void splitA_k(const float* __restrict__ src, uint32_t* __restrict__ dh,
                         uint32_t* __restrict__ dl, int M, int Kp, int lda)
{
    long idx = (long)blockIdx.x * blockDim.x + threadIdx.x;
    if (idx >= (long)M * Kp) return;
    int m = (int)(idx / Kp), kp = (int)(idx % Kp);
    float v0 = src[(long)m * lda + 2 * kp];
    float v1 = src[(long)m * lda + 2 * kp + 1];
    uint32_t lo, hi = pack_hi(v0, v1, lo);
    dh[idx] = hi; dl[idx] = lo;
}

// rkT split, tiled transpose, batched over layers via blockIdx.z
__global__ void rkTsplit_k(const float* __restrict__ rk, uint32_t* __restrict__ dh,
                           uint32_t* __restrict__ dl)
{
    int l = blockIdx.z;
    rk += (long)l * 1024 * 1024;
    dh += (long)l * 1024 * 512;
    dl += (long)l * 1024 * 512;
    __shared__ float ts[64][33];
    int nhBase = blockIdx.x * 32;
    int dBase  = blockIdx.y * 64;
    int tx = threadIdx.x, ty = threadIdx.y;   // 32 x 8
    #pragma unroll
    for (int dl_ = ty; dl_ < 64; dl_ += 8)
        ts[dl_][tx] = rk[(long)(dBase + dl_) * 1024 + nhBase + tx];
    __syncthreads();
    #pragma unroll
    for (int nl = ty; nl < 32; nl += 8) {
        uint32_t lo, hi = pack_hi(ts[2 * tx][nl], ts[2 * tx + 1][nl], lo);
        long o = (long)(nhBase + nl) * 512 + (dBase >> 1) + tx;
        dh[o] = hi; dl[o] = lo;
    }
}

// k split + bias, tiled transpose
__global__ void ksplit_k(const float* __restrict__ k, const float* __restrict__ bk,
                         uint32_t* __restrict__ dh, uint32_t* __restrict__ dl, int Lk)
{
    __shared__ float ts[32][65];
    int jBase = blockIdx.x * 32;
    int dBase = blockIdx.y * 64;
    int b = blockIdx.z;
    long per = (long)512 * Lk;
    const float* kb = k + (long)b * Lk * DMODEL;
    int tx = threadIdx.x, ty = threadIdx.y;   // 32 x 8
    #pragma unroll
    for (int jl = ty; jl < 32; jl += 8) {
        ts[jl][tx]      = kb[(long)(jBase + jl) * DMODEL + dBase + tx];
        ts[jl][tx + 32] = kb[(long)(jBase + jl) * DMODEL + dBase + tx + 32];
    }
    __syncthreads();
    #pragma unroll
    for (int dpl = ty; dpl < 32; dpl += 8) {
        float b0 = bk[dBase + 2 * dpl], b1 = bk[dBase + 2 * dpl + 1];
        uint32_t lo, hi = pack_hi(ts[tx][2 * dpl] + b0, ts[tx][2 * dpl + 1] + b1, lo);
        long o = (long)b * per + (long)((dBase >> 1) + dpl) * Lk + jBase + tx;
        dh[o] = hi; dl[o] = lo;
    }
}

// v split + bias
__global__ void vsplit_k(const float* __restrict__ v, const float* __restrict__ bv,
                         uint32_t* __restrict__ dh, uint32_t* __restrict__ dl, int Lk)
{
    long idx = (long)blockIdx.x * blockDim.x + threadIdx.x;
    long per = (long)(Lk / 2) * DMODEL;
    if (idx >= 2 * per) return;
    int b = (int)(idx / per);
    long r = idx % per;
    int jp = (int)(r / DMODEL), d = (int)(r % DMODEL);
    float bb = bv[d];
    float v0 = v[((long)b * Lk + 2 * jp) * DMODEL + d] + bb;
    float v1 = v[((long)b * Lk + 2 * jp + 1) * DMODEL + d] + bb;
    uint32_t lo, hi = pack_hi(v0, v1, lo);
    dh[(long)b * per + r] = hi;
    dl[(long)b * per + r] = lo;
}

// ---------------- relative-position basis, generated directly in split form ----
__global__ void relmat_split_k(uint32_t* __restrict__ dh, uint32_t* __restrict__ dl,
                               int nU, int nUp, int g, int d0)
{
    long idx = (long)blockIdx.x * blockDim.x + threadIdx.x;
    long tot = (long)512 * nUp;
    if (idx >= tot) return;
    int kp = (int)(idx / nUp), u = (int)(idx % nUp);
    float v0 = 0.f, v1 = 0.f;
    if (u < nU) {
        int da = 2 * kp, db_ = 2 * kp + 1;
        int fa = (da < 512) ? da : da - 512;
        int fb = (db_ < 512) ? db_ : db_ - 512;
        float invfa = expf(-(float)fa * (9.210340371976184f / 512.0f));
        float invfb = expf(-(float)fb * (9.210340371976184f / 512.0f));
        float base = (float)(g * u + d0);
        float aa = base * invfa, ab = base * invfb;
        v0 = (da < 512) ? sinf(aa) : cosf(aa);
        v1 = (db_ < 512) ? sinf(ab) : cosf(ab);
    }
    uint32_t lo, hi = pack_hi(v0, v1, lo);
    dh[idx] = hi; dl[idx] = lo;
}

// qw/qq: QSCALE*(q~ + bq + rw/rr), split output
__global__ void addbias2s_k(const float* __restrict__ q, const float* __restrict__ bq,
                            const float* __restrict__ rw, const float* __restrict__ rr,
                            uint32_t* __restrict__ qwh, uint32_t* __restrict__ qwl,
                            uint32_t* __restrict__ qqh, uint32_t* __restrict__ qql,
                            long total)
{
    long idx = (long)blockIdx.x * blockDim.x + threadIdx.x;
    if (idx >= total) return;
    long row = idx / 512;
    int d2 = (int)(idx % 512);
    int d0 = 2 * d2, d1 = d0 + 1;
    float q0 = q[row * 1024 + d0] + bq[d0], q1 = q[row * 1024 + d1] + bq[d1];
    uint32_t lo, hi;
    hi = pack_hi(QSCALE * (q0 + rw[d0]), QSCALE * (q1 + rw[d1]), lo);
    qwh[idx] = hi; qwl[idx] = lo;
    hi = pack_hi(QSCALE * (q0 + rr[d0]), QSCALE * (q1 + rr[d1]), lo);
    qqh[idx] = hi; qql[idx] = lo;
}

// token-type biases
__global__ void ttb_k(const float* __restrict__ q, const float* __restrict__ bq,
                      const float* __restrict__ rs, const float* __restrict__ seg,
                      float* __restrict__ tt0, float* __restrict__ dtt, int Lq)
{
    int idx = blockIdx.x * blockDim.x + threadIdx.x;
    if (idx >= BATCH * NHEADS * Lq) return;
    int i = idx % Lq; int bn = idx / Lq; int n = bn % NHEADS; int b = bn / NHEADS;
    const float* qp  = q + ((long)(b * Lq + i)) * DMODEL + n * DHEAD;
    const float* bqp = bq + n * DHEAD;
    const float* rsp = rs + n * DHEAD;
    const float* s0  = seg + n * DHEAD;
    const float* s1  = seg + DMODEL + n * DHEAD;
    float t0 = 0.f, t1 = 0.f;
    #pragma unroll 8
    for (int h = 0; h < DHEAD; h++) {
        float v = QSCALE * (qp[h] + bqp[h] + rsp[h]);
        t0 += v * s0[h];
        t1 += v * s1[h];
    }
    tt0[(long)bn * Lq + i] = t0;
    dtt[(long)bn * Lq + i] = t1 - t0;
}

// assemble scores (content + rel-pos gather + token-type) and softmax; split probs out
__global__ void softmax_k(const float* __restrict__ S, const float* __restrict__ P,
                          uint32_t* __restrict__ Sh, uint32_t* __restrict__ Sl,
                          const float* __restrict__ tt0, const float* __restrict__ dtt,
                          const int* __restrict__ ids,
                          int Lq, int Lk, int nU, int cq, int ck, int u0, int pq, int pk)
{
    int i = blockIdx.x, n = blockIdx.y, b = blockIdx.z;
    int bn = b * NHEADS + n;
    const float* Srow = S + ((long)bn * Lq + i) * Lk;
    const float* Prow = P + ((long)bn * Lq + i) * nU;
    float t0 = tt0[(long)bn * Lq + i], dt = dtt[(long)bn * Lq + i];
    const int* idk = ids + b * 1024;
    int idq = idk[pq * i];
    int ubase = cq * i + u0;

    __shared__ float sh[MAXTOK];
    __shared__ float red[32];
    int tid = threadIdx.x;

    float lmax = -1e30f;
    for (int j = tid; j < Lk; j += blockDim.x) {
        float tok = (idk[pk * j] == idq) ? (t0 + dt) : t0;
        float v = Srow[j] + Prow[ubase + ck * j] + tok;
        sh[j] = v;
        lmax = fmaxf(lmax, v);
    }
    float bmax = blockReduceMax(lmax, red);

    float lsum = 0.f;
    for (int j = tid; j < Lk; j += blockDim.x) {
        float e = expf(sh[j] - bmax);
        sh[j] = e;
        lsum += e;
    }
    float bsum = blockReduceSum(lsum, red);
    float inv = 1.0f / bsum;

    long srow = ((long)bn * Lq + i) * (Lk >> 1);
    for (int j2 = tid; j2 < (Lk >> 1); j2 += blockDim.x) {
        uint32_t lo, hi = pack_hi(sh[2 * j2] * inv, sh[2 * j2 + 1] * inv, lo);
        Sh[srow + j2] = hi;
        Sl[srow + j2] = lo;
    }
}

// residual + LayerNorm; writes float out + split out
__global__ void ln_k(const float* __restrict__ qin, const float* __restrict__ tmp,
                     const float* __restrict__ gvec, const float* __restrict__ bvec,
                     float* __restrict__ out, uint32_t* __restrict__ oh,
                     uint32_t* __restrict__ ol)
{
    int r = blockIdx.x, tid = threadIdx.x;
    const float* x1 = qin + (long)r * DMODEL;
    const float* x2 = tmp + (long)r * DMODEL;
    __shared__ float red[32];
    float s = 0.f;
    for (int d = tid; d < DMODEL; d += blockDim.x) s += x1[d] + x2[d];
    float mu = blockReduceSum(s, red) * (1.0f / DMODEL);
    float vs = 0.f;
    for (int d = tid; d < DMODEL; d += blockDim.x) {
        float z = x1[d] + x2[d] - mu;
        vs += z * z;
    }
    float var = blockReduceSum(vs, red) * (1.0f / DMODEL);
    float rstd = rsqrtf(var + LNEPS);
    for (int d2 = tid; d2 < 512; d2 += blockDim.x) {
        int d0 = 2 * d2, d1 = d0 + 1;
        float o0 = (x1[d0] + x2[d0] - mu) * rstd * gvec[d0] + bvec[d0];
        float o1 = (x1[d1] + x2[d1] - mu) * rstd * gvec[d1] + bvec[d1];
        out[(long)r * DMODEL + d0] = o0;
        out[(long)r * DMODEL + d1] = o1;
        uint32_t lo, hi = pack_hi(o0, o1, lo);
        oh[(long)r * 512 + d2] = hi;
        ol[(long)r * 512 + d2] = lo;
    }
}

// upsample; writes float out + split out
__global__ void upsample_k(const float* __restrict__ h, float* __restrict__ out,
                           uint32_t* __restrict__ oh, uint32_t* __restrict__ ol, int Lin)
{
    long idx = (long)blockIdx.x * blockDim.x + threadIdx.x;
    long total = (long)BATCH * Lin * 512;
    if (idx >= total) return;
    int d2 = (int)(idx % 512);
    long bt = idx / 512;
    int t = (int)(bt % Lin);
    int b = (int)(bt / Lin);
    int tp = (t == 0) ? Lin - 1 : t - 1;
    const float* cr = h + ((long)b * Lin + t) * DMODEL + 2 * d2;
    const float* pr = h + ((long)b * Lin + tp) * DMODEL + 2 * d2;
    float c0 = cr[0], c1 = cr[1];
    float i0 = 0.5f * (c0 + pr[0]), i1 = 0.5f * (c1 + pr[1]);
    long r = (long)b * (2 * Lin) + 2 * t;
    out[r * DMODEL + 2 * d2]     = c0;
    out[r * DMODEL + 2 * d2 + 1] = c1;
    out[(r + 1) * DMODEL + 2 * d2]     = i0;
    out[(r + 1) * DMODEL + 2 * d2 + 1] = i1;
    uint32_t lo, hi = pack_hi(c0, c1, lo);
    oh[r * 512 + d2] = hi; ol[r * 512 + d2] = lo;
    hi = pack_hi(i0, i1, lo);
    oh[(r + 1) * 512 + d2] = hi; ol[(r + 1) * 512 + d2] = lo;
}

// ---------------- host ----------------
static void gemmS(const uint32_t* Ah, const uint32_t* Al,
                  const uint32_t* Bh, const uint32_t* Bl,
                  const float* bias, float* C, uint32_t* Ch, uint32_t* Cl,
                  int M, int N, int Kp, int ldau, int ldbu, int ldc, int ldcs,
                  long aO, long aI, long bO, long bI, long cO, long cI,
                  int innerCount, int batches, float alpha, float biasAlpha,
                  int posWin = 0, int pcq = 0, int pck = 0, int pu0 = 0, int pLk = 0)
{
    dim3 grid((N + 127) / 128, (M + 127) / 128, batches);
    gemm_tcs<<<grid, 256>>>(Ah, Al, Bh, Bl, bias, C, Ch, Cl,
                            M, N, Kp, ldau, ldbu, ldc, ldcs,
                            aO, aI, bO, bI, cO, cI, innerCount, alpha, biasAlpha,
                            posWin, pcq, pck, pu0, pLk);
}

static void splitBP(const float* src, uint32_t* dh, uint32_t* dl,
                    int Kp, int N, int logLd, long kStr,
                    long srcBOff, long dstBOff, int nBatch)
{
    long per = (long)Kp << logLd;
    long total = per * nBatch;
    int logPer = 0;
    while ((1L << logPer) < per) logPer++;   // per is pow2 whenever nBatch > 1
    splitBP_k<<<(unsigned)((total + 255) / 256), 256>>>(
        src, dh, dl, N, logLd, kStr, srcBOff, dstBOff, nBatch, logPer, total);
}

static long relSoff(int l) {
    if (l <= 4) return (long)l * S1;
    if (l <= 8) return 5 * S1 + (long)(l - 5) * S2;
    return 5 * S1 + 4 * S2 + (long)(l - 9) * S3;
}

#define GS(sym, var) cudaGetSymbolAddress((void**)&var, sym)

extern "C" void kernel_launch(void* const* d_in, const int* in_sizes, int n_in,
                              void* d_out, int out_size)
{
    const float* final_hidden = (const float*)d_in[0];
    const int*   tok_ids      = (const int*)d_in[5];
    const float* Wq = (const float*)d_in[6];
    const float* bq = (const float*)d_in[7];
    const float* Wk = (const float*)d_in[8];
    const float* bk = (const float*)d_in[9];
    const float* Wv = (const float*)d_in[10];
    const float* bv = (const float*)d_in[11];
    const float* rw = (const float*)d_in[12];
    const float* rr = (const float*)d_in[13];
    const float* rs = (const float*)d_in[14];
    const float* rk = (const float*)d_in[15];
    const float* sg = (const float*)d_in[16];
    const float* Wp = (const float*)d_in[17];
    const float* bp = (const float*)d_in[18];
    const float* lg = (const float*)d_in[19];
    const float* lb = (const float*)d_in[20];
    float* out = (float*)d_out;

    float *p_qkv,*p_tmp,*p_hA,*p_hB,*p_up,*p_S,*p_P,*p_RELF,*p_t0,*p_dt;
    GS(g_qkv,p_qkv); GS(g_tmp,p_tmp);
    GS(g_hA,p_hA); GS(g_hB,p_hB); GS(g_up,p_up);
    GS(g_S,p_S); GS(g_P,p_P); GS(g_RELF,p_RELF);
    GS(g_tt0,p_t0); GS(g_dtt,p_dt);

    uint32_t *wch,*wcl,*wph,*wpl;
    uint32_t *r1h,*r1l,*r2h,*r2l,*r3h,*r3l,*rkth,*rktl,*relh,*rell;
    uint32_t *ksh,*ksl,*vsh,*vsl,*qwh,*qwl,*qqh,*qql,*ssh,*ssl,*vch,*vcl,*hsh,*hsl,*ush,*usl;
    GS(g_Wch,wch); GS(g_Wcl,wcl); GS(g_Wph,wph); GS(g_Wpl,wpl);
    GS(g_R1h,r1h); GS(g_R1l,r1l); GS(g_R2h,r2h); GS(g_R2l,r2l); GS(g_R3h,r3h); GS(g_R3l,r3l);
    GS(g_rkTh,rkth); GS(g_rkTl,rktl); GS(g_RELh,relh); GS(g_RELl,rell);
    GS(g_ksh,ksh); GS(g_ksl,ksl); GS(g_vsh,vsh); GS(g_vsl,vsl);
    GS(g_qwh,qwh); GS(g_qwl,qwl); GS(g_qqh,qqh); GS(g_qql,qql);
    GS(g_Ssh,ssh); GS(g_Ssl,ssl); GS(g_vch,vch); GS(g_vcl,vcl);
    GS(g_hsh,hsh); GS(g_hsl,hsl); GS(g_ush,ush); GS(g_usl,usl);

    // ---- setup: rel-pos bases + weight splits (pow2 fast-path split) ----
    relmat_split_k<<<(512*NUP1 + 255)/256, 256>>>(r1h, r1l, NU1, NUP1, 1, -1023);
    relmat_split_k<<<(512*1024 + 255)/256, 256>>>(r2h, r2l, NU2, 1024, 2, -1022);
    relmat_split_k<<<(512*512  + 255)/256, 256>>>(r3h, r3l, NU3, 512,  4, -1020);
    splitBP(Wq, wch,          wcl,          6144, 1024, 10, 1024, 0, 0, 1);
    splitBP(Wk, wch + WSPL,   wcl + WSPL,   6144, 1024, 10, 1024, 0, 0, 1);
    splitBP(Wv, wch + 2*WSPL, wcl + 2*WSPL, 6144, 1024, 10, 1024, 0, 0, 1);
    splitBP(Wp, wph, wpl, 6144, 1024, 10, 1024, 0, 0, 1);
    {
        long t = (long)512*512;
        splitA_k<<<(unsigned)((t+255)/256),256>>>(final_hidden, hsh, hsl, 512, 512, 1024);
    }

    // ---- hoisted REL pipeline: all 12 layers, batched by R-group ----
    {
        dim3 tb(32, 8), tg(32, 16, 12);
        rkTsplit_k<<<tg, tb>>>(rk, rkth, rktl);
    }
    gemmS(rkth, rktl, r1h, r1l, nullptr, p_RELF, nullptr, nullptr,
          1024, NU1, 512, 512, NUP1, NU1, 0,
          0, (long)1024*512, 0, 0, 0, F1,
          5, 5, 1.f, 0.f);
    gemmS(rkth + (long)5*1024*512, rktl + (long)5*1024*512, r2h, r2l, nullptr,
          p_RELF + 5*F1, nullptr, nullptr,
          1024, NU2, 512, 512, 1024, NU2, 0,
          0, (long)1024*512, 0, 0, 0, F2,
          4, 4, 1.f, 0.f);
    gemmS(rkth + (long)9*1024*512, rktl + (long)9*1024*512, r3h, r3l, nullptr,
          p_RELF + 5*F1 + 4*F2, nullptr, nullptr,
          1024, NU3, 512, 512, 512, NU3, 0,
          0, (long)1024*512, 0, 0, 0, F3,
          3, 3, 1.f, 0.f);
    // REL splits per group (batch = heads * layers; pow2 fast path)
    splitBP(p_RELF, relh, rell, 32, NU1, 11, NU1, (long)64*NU1, (long)32*NUP1, 80);
    splitBP(p_RELF + 5*F1, relh + 5*S1, rell + 5*S1, 32, NU2, 10, NU2,
            (long)64*NU2, (long)32*1024, 64);
    splitBP(p_RELF + 5*F1 + 4*F2, relh + 5*S1 + 4*S2, rell + 5*S1 + 4*S2, 32, NU3, 9, NU3,
            (long)64*NU3, (long)32*512, 48);

    const float* hidden = final_hidden;
    float* bufs[2] = {p_hA, p_hB};
    int pb = 0;

    for (int l = 11; l >= 0; --l) {
        int Lq, Lk, do_up, nU, nUp, cq, ck, u0, pq, pk;
        if (l <= 3)      { Lq=1024; Lk=1024; do_up=0; nU=NU1; nUp=NUP1; cq= 1; ck=-1; u0=1023; pq=1; pk=1; }
        else if (l == 4) { Lq=1024; Lk=512;  do_up=1; nU=NU1; nUp=NUP1; cq=-1; ck= 2; u0=1023; pq=1; pk=2; }
        else if (l <= 7) { Lq=512;  Lk=512;  do_up=0; nU=NU2; nUp=1024; cq= 1; ck=-1; u0=511;  pq=2; pk=2; }
        else if (l == 8) { Lq=512;  Lk=256;  do_up=1; nU=NU2; nUp=1024; cq=-1; ck= 2; u0=511;  pq=2; pk=4; }
        else             { Lq=256;  Lk=256;  do_up=0; nU=NU3; nUp=512;  cq= 1; ck=-1; u0=255;  pq=4; pk=4; }

        if (l == 11) { long t = (long)BATCH*256*512; upsample_k<<<(unsigned)((t+255)/256),256>>>(hidden, p_up, ush, usl, 256); }
        if (l == 7)  { long t = (long)BATCH*512*512; upsample_k<<<(unsigned)((t+255)/256),256>>>(hidden, p_up, ush, usl, 512); }

        const float* q_in_f = do_up ? p_up : hidden;
        uint32_t* qinh = do_up ? ush : hsh;
        uint32_t* qinl = do_up ? usl : hsl;
        uint32_t* relh_l = relh + relSoff(l);
        uint32_t* rell_l = rell + relSoff(l);

        float* p_q = p_qkv;
        float* p_k = p_qkv + QKVSTR;
        float* p_v = p_qkv + 2 * QKVSTR;

        // merged QKV projections (no bias; folded downstream)
        long WO = (long)WSPL;
        if (do_up) {
            gemmS(qinh, qinl, wch + (long)l*512*1024, wcl + (long)l*512*1024, nullptr,
                  p_q, nullptr, nullptr,
                  BATCH*Lq, DMODEL, 512, 512, 1024, DMODEL, 0,
                  0,0,0,0,0,0, 1, 1, 1.f, 0.f);
            gemmS(hsh, hsl, wch + WO + (long)l*512*1024, wcl + WO + (long)l*512*1024, nullptr,
                  p_k, nullptr, nullptr,
                  BATCH*Lk, DMODEL, 512, 512, 1024, DMODEL, 0,
                  0, 0, WO, 0, QKVSTR, 0,
                  1, 2, 1.f, 0.f);
        } else {
            gemmS(hsh, hsl, wch + (long)l*512*1024, wcl + (long)l*512*1024, nullptr,
                  p_q, nullptr, nullptr,
                  BATCH*Lq, DMODEL, 512, 512, 1024, DMODEL, 0,
                  0, 0, WO, 0, QKVSTR, 0,
                  1, 3, 1.f, 0.f);
        }

        // k/v splits (+bias); k via tiled transpose
        {
            dim3 tb(32, 8), tg(Lk / 32, 16, 2);
            ksplit_k<<<tg, tb>>>(p_k, bk + l*DMODEL, ksh, ksl, Lk);
            long t = (long)2*(Lk/2)*DMODEL;
            vsplit_k<<<(unsigned)((t+255)/256),256>>>(p_v, bv + l*DMODEL, vsh, vsl, Lk);
        }
        // qw/qq splits (+bq, scaled)
        {
            long t = (long)BATCH*Lq*512;
            addbias2s_k<<<(unsigned)((t+255)/256),256>>>(p_q, bq + l*DMODEL,
                                                         rw + l*DMODEL, rr + l*DMODEL,
                                                         qwh, qwl, qqh, qql, t);
        }
        // token-type biases
        {
            int t = BATCH*NHEADS*Lq;
            ttb_k<<<(t+255)/256, 256>>>(p_q, bq + l*DMODEL, rs + l*DMODEL,
                                        sg + (long)l*2*DMODEL, p_t0, p_dt, Lq);
        }

        // content scores -> S
        gemmS(qwh, qwl, ksh, ksl, nullptr, p_S, nullptr, nullptr,
              Lq, Lk, 32, 512, Lk, Lk, 0,
              (long)Lq*512, 32, (long)512*Lk, (long)32*Lk,
              (long)NHEADS*Lq*Lk, (long)Lq*Lk,
              NHEADS, BATCH*NHEADS, 1.f, 0.f);

        // P (rel-pos projections), window-culled
        gemmS(qqh, qql, relh_l, rell_l, nullptr, p_P, nullptr, nullptr,
              Lq, nU, 32, 512, nUp, nU, 0,
              (long)Lq*512, 32, 0, (long)32*nUp,
              (long)NHEADS*Lq*nU, (long)Lq*nU,
              NHEADS, BATCH*NHEADS, 1.f, 0.f,
              1, cq, ck, u0, Lk);

        // softmax (gathers P band, writes split probs)
        {
            dim3 grid(Lq, NHEADS, BATCH);
            softmax_k<<<grid, 256>>>(p_S, p_P, ssh, ssl, p_t0, p_dt, tok_ids,
                                     Lq, Lk, nU, cq, ck, u0, pq, pk);
        }

        // vec = prob @ v (split output)
        gemmS(ssh, ssl, vsh, vsl, nullptr, nullptr, vch, vcl,
              Lq, DHEAD, Lk/2, Lk/2, DMODEL, 0, 512,
              (long)NHEADS*Lq*(Lk/2), (long)Lq*(Lk/2),
              (long)(Lk/2)*DMODEL, 64,
              (long)Lq*512, 32,
              NHEADS, BATCH*NHEADS, 1.f, 0.f);

        // post projection
        gemmS(vch, vcl, wph + (long)l*512*1024, wpl + (long)l*512*1024, bp + l*DMODEL,
              p_tmp, nullptr, nullptr,
              BATCH*Lq, DMODEL, 512, 512, 1024, DMODEL, 0,
              0,0,0,0,0,0, 1, 1, 1.f, 1.f);

        // residual + LayerNorm (writes float hidden + split hidden)
        float* dst = (l == 0) ? out : bufs[pb];
        ln_k<<<BATCH*Lq, 256>>>(q_in_f, p_tmp, lg + l*DMODEL, lb + l*DMODEL, dst, hsh, hsl);

        hidden = dst;
        pb ^= 1;
    }
}